// round 3
// baseline (speedup 1.0000x reference)
#include <cuda_runtime.h>
#include <cstdint>

// Problem constants
#define B_    4
#define L_    4096
#define C_    1024
#define H_    16
#define D_    64
#define MTOT  (B_*L_)      // 16384

// ---------------- scratch (device globals; no allocations allowed) ----------
__device__ float g_q[MTOT * C_];          // 64 MB
__device__ float g_k[MTOT * C_];          // 64 MB
__device__ float g_v[MTOT * C_];          // 64 MB
__device__ float g_kvp[64 * 8 * D_ * D_]; // partial kv per (b,h,chunk): 8 MB
__device__ float g_skp[64 * 8 * D_];      // partial summed_k
__device__ float g_kv[64 * D_ * D_];      // reduced kv
__device__ float g_sk[64 * D_];           // reduced summed_k

// ---------------- tf32 mma helpers ------------------------------------------
__device__ __forceinline__ uint32_t f2tf32(float f) {
    uint32_t u;
    asm("cvt.rna.tf32.f32 %0, %1;" : "=r"(u) : "f"(f));
    return u;
}

__device__ __forceinline__ void mma_tf32(float c[4],
        uint32_t a0, uint32_t a1, uint32_t a2, uint32_t a3,
        uint32_t b0, uint32_t b1) {
    asm volatile(
        "mma.sync.aligned.m16n8k8.row.col.f32.tf32.tf32.f32 "
        "{%0,%1,%2,%3}, {%4,%5,%6,%7}, {%8,%9}, {%0,%1,%2,%3};\n"
        : "+f"(c[0]), "+f"(c[1]), "+f"(c[2]), "+f"(c[3])
        : "r"(a0), "r"(a1), "r"(a2), "r"(a3), "r"(b0), "r"(b1));
}

__device__ __forceinline__ void cp16(uint32_t saddr, const void* gaddr) {
    asm volatile("cp.async.cg.shared.global [%0], [%1], 16;\n"
                 :: "r"(saddr), "l"(gaddr));
}

// ---------------- projection GEMM: out = X @ W^T + b, fused epilogue --------
// MODE 0: Q (elu+1, * mask) ; MODE 1: K (elu+1, * mask) ; MODE 2: V (* mask)
// 128x256x16 tile, 4-stage cp.async pipeline, 8 warps (2 M x 4 N, 64x64 each).
#define PBM 128
#define PBN 256
#define PBK 16
#define PSTR 20                 // floats per smem row: 80B, 16B-aligned, conflict-free
#define ASTG (PBM * PSTR)       // 2560 floats per A stage
#define BSTG (PBN * PSTR)       // 5120 floats per B stage
#define NSTAGE 4
#define NKT (C_ / PBK)          // 64 k-iterations
#define PROJ_SMEM_BYTES (NSTAGE * (ASTG + BSTG) * 4)   // 122880 B

template <int MODE>
__global__ __launch_bounds__(256, 1) void proj_kernel(
        const float* __restrict__ X, const float* __restrict__ W,
        const float* __restrict__ bias, const float* __restrict__ mask) {
    float* out = (MODE == 0) ? g_q : (MODE == 1) ? g_k : g_v;

    extern __shared__ float ps[];
    float* As = ps;                     // NSTAGE * ASTG
    float* Bs = ps + NSTAGE * ASTG;     // NSTAGE * BSTG

    const int tid  = threadIdx.x;
    const int warp = tid >> 5;
    const int lane = tid & 31;
    const int wm   = warp & 1;    // 2 warps along M (64 rows each)
    const int wn   = warp >> 1;   // 4 warps along N (64 cols each)
    const int gid  = lane >> 2;
    const int tig  = lane & 3;
    const int m0   = blockIdx.y * PBM;
    const int n0   = blockIdx.x * PBN;

    // copy mapping. A: thread t -> row t>>1, float-col (t&1)*8, 2x cp16.
    //               B: thread t -> row t, 4x cp16 (full 16-float row).
    const int arow = tid >> 1;
    const int acol = (tid & 1) * 8;
    const float* gA = X + (size_t)(m0 + arow) * C_ + acol;
    const float* gB = W + (size_t)(n0 + tid) * C_;
    const uint32_t sAb = (uint32_t)__cvta_generic_to_shared(As);
    const uint32_t sBb = (uint32_t)__cvta_generic_to_shared(Bs);
    const uint32_t sA  = sAb + (uint32_t)(arow * PSTR + acol) * 4u;
    const uint32_t sB  = sBb + (uint32_t)(tid * PSTR) * 4u;

    float acc[4][8][4];
#pragma unroll
    for (int i = 0; i < 4; i++)
#pragma unroll
        for (int j = 0; j < 8; j++)
#pragma unroll
            for (int r = 0; r < 4; r++) acc[i][j][r] = 0.f;

    // prologue: stages 0..2
#pragma unroll
    for (int s = 0; s < NSTAGE - 1; s++) {
        const int k0 = s * PBK;
        const uint32_t ao = (uint32_t)(s * ASTG) * 4u;
        const uint32_t bo = (uint32_t)(s * BSTG) * 4u;
        cp16(sA + ao,      gA + k0);
        cp16(sA + ao + 16, gA + k0 + 4);
        cp16(sB + bo,      gB + k0);
        cp16(sB + bo + 16, gB + k0 + 4);
        cp16(sB + bo + 32, gB + k0 + 8);
        cp16(sB + bo + 48, gB + k0 + 12);
        asm volatile("cp.async.commit_group;\n" ::: "memory");
    }

    for (int kt = 0; kt < NKT; kt++) {
        if (kt + 3 < NKT) {
            const int s = (kt + 3) & (NSTAGE - 1);
            const int k0 = (kt + 3) * PBK;
            const uint32_t ao = (uint32_t)(s * ASTG) * 4u;
            const uint32_t bo = (uint32_t)(s * BSTG) * 4u;
            cp16(sA + ao,      gA + k0);
            cp16(sA + ao + 16, gA + k0 + 4);
            cp16(sB + bo,      gB + k0);
            cp16(sB + bo + 16, gB + k0 + 4);
            cp16(sB + bo + 32, gB + k0 + 8);
            cp16(sB + bo + 48, gB + k0 + 12);
            asm volatile("cp.async.commit_group;\n" ::: "memory");
            asm volatile("cp.async.wait_group 3;\n" ::: "memory");
        } else if (kt + 2 < NKT) {
            asm volatile("cp.async.wait_group 2;\n" ::: "memory");
        } else if (kt + 1 < NKT) {
            asm volatile("cp.async.wait_group 1;\n" ::: "memory");
        } else {
            asm volatile("cp.async.wait_group 0;\n" ::: "memory");
        }
        __syncthreads();

        const float* a_s = As + (kt & (NSTAGE - 1)) * ASTG;
        const float* b_s = Bs + (kt & (NSTAGE - 1)) * BSTG;

#pragma unroll
        for (int ks = 0; ks < PBK / 8; ks++) {
            const int kk = ks * 8;
            uint32_t a[4][4], b[8][2];
#pragma unroll
            for (int mt = 0; mt < 4; mt++) {
                const int r0 = wm * 64 + mt * 16;
                a[mt][0] = f2tf32(a_s[(r0 + gid    ) * PSTR + kk + tig    ]);
                a[mt][1] = f2tf32(a_s[(r0 + gid + 8) * PSTR + kk + tig    ]);
                a[mt][2] = f2tf32(a_s[(r0 + gid    ) * PSTR + kk + tig + 4]);
                a[mt][3] = f2tf32(a_s[(r0 + gid + 8) * PSTR + kk + tig + 4]);
            }
#pragma unroll
            for (int nt = 0; nt < 8; nt++) {
                const int c0 = wn * 64 + nt * 8;
                b[nt][0] = f2tf32(b_s[(c0 + gid) * PSTR + kk + tig    ]);
                b[nt][1] = f2tf32(b_s[(c0 + gid) * PSTR + kk + tig + 4]);
            }
#pragma unroll
            for (int mt = 0; mt < 4; mt++)
#pragma unroll
                for (int nt = 0; nt < 8; nt++)
                    mma_tf32(acc[mt][nt], a[mt][0], a[mt][1], a[mt][2], a[mt][3],
                             b[nt][0], b[nt][1]);
        }
        __syncthreads();
    }

    // epilogue: +bias, feature map (Q/K), per-token mask; float2 stores
#pragma unroll
    for (int mt = 0; mt < 4; mt++) {
#pragma unroll
        for (int nt = 0; nt < 8; nt++) {
#pragma unroll
            for (int half = 0; half < 2; half++) {
                const int row = m0 + wm * 64 + mt * 16 + gid + half * 8;
                const int col = n0 + wn * 64 + nt * 8 + tig * 2;
                float v0 = acc[mt][nt][half * 2 + 0] + bias[col + 0];
                float v1 = acc[mt][nt][half * 2 + 1] + bias[col + 1];
                if (MODE < 2) {
                    v0 = (v0 > 0.f) ? v0 + 1.f : expf(v0);
                    v1 = (v1 > 0.f) ? v1 + 1.f : expf(v1);
                }
                const float mk = mask[row];
                v0 *= mk; v1 *= mk;
                float2 o = make_float2(v0, v1);
                *(float2*)&out[(size_t)row * C_ + col] = o;
            }
        }
    }
}

// ---------------- phase 2: partial kv = K^T V via tf32 mma ------------------
// Per (bh, chunk): kv64x64 += K_chunk^T @ V_chunk, K=512.
// 4 warps; warp w owns output cols [w*16, w*16+16). Plus summed_k.
#define KSTR 72   // smem row stride (floats): tig*8+gid hits 32 distinct banks

__global__ __launch_bounds__(128) void kv_kernel() {
    const int bh = blockIdx.x;   // 0..63 (b*16+h)
    const int ch = blockIdx.y;   // 0..7  (L chunk of 512)
    const int b = bh >> 4, h = bh & 15;

    __shared__ float Ks[64][KSTR];
    __shared__ float Vs[64][KSTR];

    const int tid  = threadIdx.x;
    const int warp = tid >> 5;
    const int lane = tid & 31;
    const int gid  = lane >> 2;
    const int tig  = lane & 3;

    const size_t base = ((size_t)b * L_ + ch * 512) * C_ + h * D_;
    const float* kb = g_k + base;
    const float* vb = g_v + base;

    float acc[4][2][4];
#pragma unroll
    for (int i = 0; i < 4; i++)
#pragma unroll
        for (int j = 0; j < 2; j++)
#pragma unroll
            for (int r = 0; r < 4; r++) acc[i][j][r] = 0.f;
    float sk = 0.f;

    for (int t0 = 0; t0 < 512; t0 += 64) {
        // load 64 tokens x 64 floats of K and V (each thread: 8 float4 per array)
#pragma unroll
        for (int i = 0; i < 8; i++) {
            const int idx = tid + i * 128;          // float4 index 0..1023
            const int r = idx >> 4, c = (idx & 15) * 4;
            *(float4*)&Ks[r][c] = *(const float4*)&kb[(size_t)(t0 + r) * C_ + c];
            *(float4*)&Vs[r][c] = *(const float4*)&vb[(size_t)(t0 + r) * C_ + c];
        }
        __syncthreads();

        if (tid < 64) {
#pragma unroll 8
            for (int l = 0; l < 64; l++) sk += Ks[l][tid];
        }

        // mma: A[d][l] = Ks[l][d], B[e][l] = Vs[l][e]
#pragma unroll
        for (int kk = 0; kk < 64; kk += 8) {
            uint32_t a[4][4], bfr[2][2];
#pragma unroll
            for (int mt = 0; mt < 4; mt++) {
                const int r0 = mt * 16;
                a[mt][0] = f2tf32(Ks[kk + tig    ][r0 + gid    ]);
                a[mt][1] = f2tf32(Ks[kk + tig    ][r0 + gid + 8]);
                a[mt][2] = f2tf32(Ks[kk + tig + 4][r0 + gid    ]);
                a[mt][3] = f2tf32(Ks[kk + tig + 4][r0 + gid + 8]);
            }
#pragma unroll
            for (int nt = 0; nt < 2; nt++) {
                const int c0 = warp * 16 + nt * 8;
                bfr[nt][0] = f2tf32(Vs[kk + tig    ][c0 + gid]);
                bfr[nt][1] = f2tf32(Vs[kk + tig + 4][c0 + gid]);
            }
#pragma unroll
            for (int mt = 0; mt < 4; mt++)
#pragma unroll
                for (int nt = 0; nt < 2; nt++)
                    mma_tf32(acc[mt][nt], a[mt][0], a[mt][1], a[mt][2], a[mt][3],
                             bfr[nt][0], bfr[nt][1]);
        }
        __syncthreads();
    }

    float* outp = g_kvp + (size_t)(bh * 8 + ch) * D_ * D_;
#pragma unroll
    for (int mt = 0; mt < 4; mt++) {
#pragma unroll
        for (int nt = 0; nt < 2; nt++) {
#pragma unroll
            for (int half = 0; half < 2; half++) {
                const int d = mt * 16 + gid + half * 8;
                const int e = warp * 16 + nt * 8 + tig * 2;
                float2 o = make_float2(acc[mt][nt][half * 2 + 0],
                                       acc[mt][nt][half * 2 + 1]);
                *(float2*)&outp[d * D_ + e] = o;
            }
        }
    }
    if (tid < 64) g_skp[(bh * 8 + ch) * D_ + tid] = sk;
}

// ---------------- phase 2b: reduce chunk partials ---------------------------
__global__ __launch_bounds__(256) void reduce_kernel() {
    const int bh = blockIdx.x;
    const int tid = threadIdx.x;
    for (int idx = tid; idx < D_ * D_; idx += 256) {
        float s = 0.f;
#pragma unroll
        for (int c = 0; c < 8; c++) s += g_kvp[(size_t)(bh * 8 + c) * D_ * D_ + idx];
        g_kv[(size_t)bh * D_ * D_ + idx] = s;
    }
    if (tid < 64) {
        float s = 0.f;
#pragma unroll
        for (int c = 0; c < 8; c++) s += g_skp[(bh * 8 + c) * D_ + tid];
        g_sk[bh * D_ + tid] = s;
    }
}

// ---------------- phase 3: out = (q @ kv) * denom ---------------------------
__global__ __launch_bounds__(256) void out_kernel(float* __restrict__ out) {
    const int bh = blockIdx.x;   // 0..63
    const int lc = blockIdx.y;   // 0..63 (L tile of 64)
    const int b = bh >> 4, h = bh & 15;

    __shared__ float qs[64][68];
    __shared__ float kvs[64][68];
    __shared__ float sks[64];
    __shared__ float den[64];

    const int tid = threadIdx.x;
    const int tx = tid & 15, ty = tid >> 4;
    const int lr = tid >> 4, lv = tid & 15;

    const float* qb = g_q + ((size_t)b * L_ + lc * 64) * C_ + h * D_;
#pragma unroll
    for (int i = 0; i < 4; i++) {
        const int r = lr + i * 16;
        *(float4*)&qs[r][lv * 4]  = *(const float4*)&qb[(size_t)r * C_ + lv * 4];
        *(float4*)&kvs[r][lv * 4] = *(const float4*)&g_kv[(size_t)bh * D_ * D_ + r * D_ + lv * 4];
    }
    if (tid < 64) sks[tid] = g_sk[bh * D_ + tid];
    __syncthreads();

    if (tid < 64) {
        float s = 0.f;
#pragma unroll 16
        for (int d = 0; d < 64; d++) s += qs[tid][d] * sks[d];
        den[tid] = 1.f / (1e-6f + s);
    }
    __syncthreads();

    float acc[4][4];
#pragma unroll
    for (int i = 0; i < 4; i++)
#pragma unroll
        for (int j = 0; j < 4; j++) acc[i][j] = 0.f;

#pragma unroll 4
    for (int d = 0; d < 64; d++) {
        const float4 kv4 = *(const float4*)&kvs[d][tx * 4];
#pragma unroll
        for (int i = 0; i < 4; i++) {
            const float qv = qs[ty * 4 + i][d];
            acc[i][0] += qv * kv4.x; acc[i][1] += qv * kv4.y;
            acc[i][2] += qv * kv4.z; acc[i][3] += qv * kv4.w;
        }
    }

#pragma unroll
    for (int i = 0; i < 4; i++) {
        const int l = lc * 64 + ty * 4 + i;
        const float dn = den[ty * 4 + i];
        float4 o = make_float4(acc[i][0] * dn, acc[i][1] * dn,
                               acc[i][2] * dn, acc[i][3] * dn);
        *(float4*)&out[((size_t)b * L_ + l) * C_ + h * D_ + tx * 4] = o;
    }
}

// ---------------- launch ----------------------------------------------------
extern "C" void kernel_launch(void* const* d_in, const int* in_sizes, int n_in,
                              void* d_out, int out_size) {
    const float* query   = (const float*)d_in[0];
    const float* key     = (const float*)d_in[1];
    const float* value   = (const float*)d_in[2];
    const float* mask_q  = (const float*)d_in[3];
    const float* mask_kv = (const float*)d_in[4];
    const float* Wq = (const float*)d_in[5];
    const float* bq = (const float*)d_in[6];
    const float* Wk = (const float*)d_in[7];
    const float* bk = (const float*)d_in[8];
    const float* Wv = (const float*)d_in[9];
    const float* bv = (const float*)d_in[10];
    float* out = (float*)d_out;

    static bool attr_done = false;
    if (!attr_done) {
        cudaFuncSetAttribute(proj_kernel<0>,
            cudaFuncAttributeMaxDynamicSharedMemorySize, PROJ_SMEM_BYTES);
        cudaFuncSetAttribute(proj_kernel<1>,
            cudaFuncAttributeMaxDynamicSharedMemorySize, PROJ_SMEM_BYTES);
        cudaFuncSetAttribute(proj_kernel<2>,
            cudaFuncAttributeMaxDynamicSharedMemorySize, PROJ_SMEM_BYTES);
        attr_done = true;
    }

    dim3 pg(C_ / PBN, MTOT / PBM);   // (4, 128)
    proj_kernel<0><<<pg, 256, PROJ_SMEM_BYTES>>>(query, Wq, bq, mask_q);
    proj_kernel<1><<<pg, 256, PROJ_SMEM_BYTES>>>(key,   Wk, bk, mask_kv);
    proj_kernel<2><<<pg, 256, PROJ_SMEM_BYTES>>>(value, Wv, bv, mask_kv);

    kv_kernel<<<dim3(64, 8), 128>>>();
    reduce_kernel<<<64, 256>>>();
    out_kernel<<<dim3(64, 64), 256>>>(out);
}

// round 6
// speedup vs baseline: 2.1205x; 2.1205x over previous
#include <cuda_runtime.h>
#include <cuda_fp16.h>
#include <cstdint>

// Problem constants
#define B_    4
#define L_    4096
#define C_    1024
#define H_    16
#define D_    64
#define MTOT  (B_*L_)      // 16384

// ---------------- scratch (device globals; no allocations allowed) ----------
__device__ float  g_q[MTOT * C_];          // 64 MB
__device__ float  g_k[MTOT * C_];          // 64 MB
__device__ float  g_v[MTOT * C_];          // 64 MB
__device__ __half g_xh[MTOT * C_];         // 32 MB (fp16 input, reused per proj)
__device__ __half g_wh[C_ * C_];           // 2 MB  (fp16 weight, reused per proj)
__device__ float  g_kvp[64 * 8 * D_ * D_]; // partial kv per (b,h,chunk)
__device__ float  g_skp[64 * 8 * D_];      // partial summed_k
__device__ float  g_kv[64 * D_ * D_];      // reduced kv
__device__ float  g_sk[64 * D_];           // reduced summed_k

// ---------------- helpers ----------------------------------------------------
__device__ __forceinline__ uint32_t f2tf32(float f) {
    uint32_t u;
    asm("cvt.rna.tf32.f32 %0, %1;" : "=r"(u) : "f"(f));
    return u;
}

__device__ __forceinline__ void mma_tf32(float c[4],
        uint32_t a0, uint32_t a1, uint32_t a2, uint32_t a3,
        uint32_t b0, uint32_t b1) {
    asm volatile(
        "mma.sync.aligned.m16n8k8.row.col.f32.tf32.tf32.f32 "
        "{%0,%1,%2,%3}, {%4,%5,%6,%7}, {%8,%9}, {%0,%1,%2,%3};\n"
        : "+f"(c[0]), "+f"(c[1]), "+f"(c[2]), "+f"(c[3])
        : "r"(a0), "r"(a1), "r"(a2), "r"(a3), "r"(b0), "r"(b1));
}

__device__ __forceinline__ void mma_f16(float c[4],
        uint32_t a0, uint32_t a1, uint32_t a2, uint32_t a3,
        uint32_t b0, uint32_t b1) {
    asm volatile(
        "mma.sync.aligned.m16n8k16.row.col.f32.f16.f16.f32 "
        "{%0,%1,%2,%3}, {%4,%5,%6,%7}, {%8,%9}, {%0,%1,%2,%3};\n"
        : "+f"(c[0]), "+f"(c[1]), "+f"(c[2]), "+f"(c[3])
        : "r"(a0), "r"(a1), "r"(a2), "r"(a3), "r"(b0), "r"(b1));
}

__device__ __forceinline__ void cp16(uint32_t saddr, const void* gaddr) {
    asm volatile("cp.async.cg.shared.global [%0], [%1], 16;\n"
                 :: "r"(saddr), "l"(gaddr));
}

__device__ __forceinline__ void ldsm_x4(uint32_t& r0, uint32_t& r1,
                                        uint32_t& r2, uint32_t& r3,
                                        uint32_t addr) {
    asm volatile("ldmatrix.sync.aligned.m8n8.x4.shared.b16 {%0,%1,%2,%3}, [%4];"
                 : "=r"(r0), "=r"(r1), "=r"(r2), "=r"(r3) : "r"(addr));
}

__device__ __forceinline__ void ldsm_x2(uint32_t& r0, uint32_t& r1,
                                        uint32_t addr) {
    asm volatile("ldmatrix.sync.aligned.m8n8.x2.shared.b16 {%0,%1}, [%2];"
                 : "=r"(r0), "=r"(r1) : "r"(addr));
}

#define SW128(off) ((off) ^ ((((uint32_t)(off)) >> 3) & 0x70))

// ---------------- fp32 -> fp16 conversion ------------------------------------
// DST 0: g_xh ; DST 1: g_wh  (device-symbol destinations; no host symbol query)
template <int DST>
__global__ __launch_bounds__(256) void cvt_kernel(
        const float* __restrict__ src, int n4) {
    __half* dst = (DST == 0) ? g_xh : g_wh;
    int i = blockIdx.x * blockDim.x + threadIdx.x;
    if (i < n4) {
        float4 v = ((const float4*)src)[i];
        __half2 h0 = __floats2half2_rn(v.x, v.y);
        __half2 h1 = __floats2half2_rn(v.z, v.w);
        ((__half2*)dst)[2 * i]     = h0;
        ((__half2*)dst)[2 * i + 1] = h1;
    }
}

// ---------------- projection GEMM (fp16 mma): out = X @ W^T + b --------------
// MODE 0: Q (elu+1, *mask) ; MODE 1: K (elu+1, *mask) ; MODE 2: V (*mask)
// 128x128 tile, BK=64 halves (128B rows, SW128), 3-stage cp.async,
// ldmatrix fragment loads, 8 warps (2M x 4N -> 64x32 warp tile).
#define HBM_ 128
#define HBN_ 128
#define HBK_ 64                   // halves per k-slab
#define HSTG_BYTES (128 * 128)    // 16 KB per operand per stage
#define HNSTAGE 3
#define HNKT (C_ / HBK_)          // 16
#define PROJ_SMEM (HNSTAGE * 2 * HSTG_BYTES)   // 98304 B

template <int MODE>
__global__ __launch_bounds__(256, 2) void proj_h(
        const float* __restrict__ bias, const float* __restrict__ mask) {
    float* out = (MODE == 0) ? g_q : (MODE == 1) ? g_k : g_v;
    const __half* __restrict__ Xh = g_xh;
    const __half* __restrict__ Wh = g_wh;

    extern __shared__ char smem[];
    const uint32_t sb = (uint32_t)__cvta_generic_to_shared(smem);
    // stage layout: [A0 B0 A1 B1 A2 B2], 16KB each
    const int tid  = threadIdx.x;
    const int warp = tid >> 5;
    const int lane = tid & 31;
    const int wm   = warp & 1;    // 2 warps along M (64 rows)
    const int wn   = warp >> 1;   // 4 warps along N (32 cols)
    const int m0   = blockIdx.y * HBM_;
    const int n0   = blockIdx.x * HBN_;

    // copy mapping: thread t -> row t>>1, chunks (t&1)*4 .. +3 (16B each)
    const int crow = tid >> 1;
    const int cch0 = (tid & 1) * 4;
    const __half* gA = Xh + (size_t)(m0 + crow) * C_ + cch0 * 8;
    const __half* gB = Wh + (size_t)(n0 + crow) * C_ + cch0 * 8;

    auto fill = [&](int stg, int s) {
        const int k0 = s * HBK_;
        const uint32_t sA = sb + (uint32_t)(stg * 2) * HSTG_BYTES;
        const uint32_t sB = sA + HSTG_BYTES;
#pragma unroll
        for (int c = 0; c < 4; c++) {
            const uint32_t off = SW128((uint32_t)(crow * 128 + (cch0 + c) * 16));
            cp16(sA + off, gA + k0 + c * 8);
            cp16(sB + off, gB + k0 + c * 8);
        }
        asm volatile("cp.async.commit_group;\n" ::: "memory");
    };

    float acc[4][4][4];
#pragma unroll
    for (int i = 0; i < 4; i++)
#pragma unroll
        for (int j = 0; j < 4; j++)
#pragma unroll
            for (int r = 0; r < 4; r++) acc[i][j][r] = 0.f;

    // ldmatrix per-thread base offsets (bytes within operand stage)
    const int lm  = lane & 15;
    const int lka = (lane >> 4) * 16;        // A: k-group byte offset
    const int lnb = lane & 7;
    const int lkb = ((lane >> 3) & 1) * 16;  // B: k-group byte offset
    uint32_t offA[4], offB[4];
#pragma unroll
    for (int mt = 0; mt < 4; mt++)
        offA[mt] = (uint32_t)((wm * 64 + mt * 16 + lm) * 128 + lka);
#pragma unroll
    for (int nt = 0; nt < 4; nt++)
        offB[nt] = (uint32_t)((wn * 32 + nt * 8 + lnb) * 128 + lkb);

    // prologue: stages 0,1
    fill(0, 0);
    fill(1, 1);

    for (int kt = 0; kt < HNKT; kt++) {
        if (kt + 2 < HNKT) {
            fill((kt + 2) % HNSTAGE, kt + 2);
            asm volatile("cp.async.wait_group 2;\n" ::: "memory");
        } else if (kt + 1 < HNKT) {
            asm volatile("cp.async.wait_group 1;\n" ::: "memory");
        } else {
            asm volatile("cp.async.wait_group 0;\n" ::: "memory");
        }
        __syncthreads();

        const int stg = kt % HNSTAGE;
        const uint32_t sA = sb + (uint32_t)(stg * 2) * HSTG_BYTES;
        const uint32_t sB = sA + HSTG_BYTES;

#pragma unroll
        for (int ks = 0; ks < 4; ks++) {          // 4 k-steps of 16 halves
            const uint32_t kb = (uint32_t)(ks * 32);
            uint32_t a[4][4], b[4][2];
#pragma unroll
            for (int mt = 0; mt < 4; mt++)
                ldsm_x4(a[mt][0], a[mt][1], a[mt][2], a[mt][3],
                        sA + SW128(offA[mt] + kb));
#pragma unroll
            for (int nt = 0; nt < 4; nt++)
                ldsm_x2(b[nt][0], b[nt][1], sB + SW128(offB[nt] + kb));
#pragma unroll
            for (int mt = 0; mt < 4; mt++)
#pragma unroll
                for (int nt = 0; nt < 4; nt++)
                    mma_f16(acc[mt][nt], a[mt][0], a[mt][1], a[mt][2], a[mt][3],
                            b[nt][0], b[nt][1]);
        }
        __syncthreads();
    }

    // epilogue: +bias, feature map (Q/K), per-token mask; float2 stores
#pragma unroll
    for (int mt = 0; mt < 4; mt++) {
#pragma unroll
        for (int nt = 0; nt < 4; nt++) {
#pragma unroll
            for (int half = 0; half < 2; half++) {
                const int row = m0 + wm * 64 + mt * 16 + (lane >> 2) + half * 8;
                const int col = n0 + wn * 32 + nt * 8 + (lane & 3) * 2;
                float v0 = acc[mt][nt][half * 2 + 0] + bias[col + 0];
                float v1 = acc[mt][nt][half * 2 + 1] + bias[col + 1];
                if (MODE < 2) {
                    v0 = (v0 > 0.f) ? v0 + 1.f : expf(v0);
                    v1 = (v1 > 0.f) ? v1 + 1.f : expf(v1);
                }
                const float mk = mask[row];
                v0 *= mk; v1 *= mk;
                float2 o = make_float2(v0, v1);
                *(float2*)&out[(size_t)row * C_ + col] = o;
            }
        }
    }
}

// ---------------- phase 2: partial kv = K^T V via tf32 mma ------------------
#define KSTR 72

__global__ __launch_bounds__(128) void kv_kernel() {
    const int bh = blockIdx.x;
    const int ch = blockIdx.y;
    const int b = bh >> 4, h = bh & 15;

    __shared__ float Ks[64][KSTR];
    __shared__ float Vs[64][KSTR];

    const int tid  = threadIdx.x;
    const int warp = tid >> 5;
    const int lane = tid & 31;
    const int gid  = lane >> 2;
    const int tig  = lane & 3;

    const size_t base = ((size_t)b * L_ + ch * 512) * C_ + h * D_;
    const float* kb = g_k + base;
    const float* vb = g_v + base;

    float acc[4][2][4];
#pragma unroll
    for (int i = 0; i < 4; i++)
#pragma unroll
        for (int j = 0; j < 2; j++)
#pragma unroll
            for (int r = 0; r < 4; r++) acc[i][j][r] = 0.f;
    float sk = 0.f;

    for (int t0 = 0; t0 < 512; t0 += 64) {
#pragma unroll
        for (int i = 0; i < 8; i++) {
            const int idx = tid + i * 128;
            const int r = idx >> 4, c = (idx & 15) * 4;
            *(float4*)&Ks[r][c] = *(const float4*)&kb[(size_t)(t0 + r) * C_ + c];
            *(float4*)&Vs[r][c] = *(const float4*)&vb[(size_t)(t0 + r) * C_ + c];
        }
        __syncthreads();

        if (tid < 64) {
#pragma unroll 8
            for (int l = 0; l < 64; l++) sk += Ks[l][tid];
        }

#pragma unroll
        for (int kk = 0; kk < 64; kk += 8) {
            uint32_t a[4][4], bfr[2][2];
#pragma unroll
            for (int mt = 0; mt < 4; mt++) {
                const int r0 = mt * 16;
                a[mt][0] = f2tf32(Ks[kk + tig    ][r0 + gid    ]);
                a[mt][1] = f2tf32(Ks[kk + tig    ][r0 + gid + 8]);
                a[mt][2] = f2tf32(Ks[kk + tig + 4][r0 + gid    ]);
                a[mt][3] = f2tf32(Ks[kk + tig + 4][r0 + gid + 8]);
            }
#pragma unroll
            for (int nt = 0; nt < 2; nt++) {
                const int c0 = warp * 16 + nt * 8;
                bfr[nt][0] = f2tf32(Vs[kk + tig    ][c0 + gid]);
                bfr[nt][1] = f2tf32(Vs[kk + tig + 4][c0 + gid]);
            }
#pragma unroll
            for (int mt = 0; mt < 4; mt++)
#pragma unroll
                for (int nt = 0; nt < 2; nt++)
                    mma_tf32(acc[mt][nt], a[mt][0], a[mt][1], a[mt][2], a[mt][3],
                             bfr[nt][0], bfr[nt][1]);
        }
        __syncthreads();
    }

    float* outp = g_kvp + (size_t)(bh * 8 + ch) * D_ * D_;
#pragma unroll
    for (int mt = 0; mt < 4; mt++) {
#pragma unroll
        for (int nt = 0; nt < 2; nt++) {
#pragma unroll
            for (int half = 0; half < 2; half++) {
                const int d = mt * 16 + gid + half * 8;
                const int e = warp * 16 + nt * 8 + tig * 2;
                float2 o = make_float2(acc[mt][nt][half * 2 + 0],
                                       acc[mt][nt][half * 2 + 1]);
                *(float2*)&outp[d * D_ + e] = o;
            }
        }
    }
    if (tid < 64) g_skp[(bh * 8 + ch) * D_ + tid] = sk;
}

// ---------------- phase 2b: reduce chunk partials ---------------------------
__global__ __launch_bounds__(256) void reduce_kernel() {
    const int bh = blockIdx.x;
    const int tid = threadIdx.x;
    for (int idx = tid; idx < D_ * D_; idx += 256) {
        float s = 0.f;
#pragma unroll
        for (int c = 0; c < 8; c++) s += g_kvp[(size_t)(bh * 8 + c) * D_ * D_ + idx];
        g_kv[(size_t)bh * D_ * D_ + idx] = s;
    }
    if (tid < 64) {
        float s = 0.f;
#pragma unroll
        for (int c = 0; c < 8; c++) s += g_skp[(bh * 8 + c) * D_ + tid];
        g_sk[bh * D_ + tid] = s;
    }
}

// ---------------- phase 3: out = (q @ kv) * denom ---------------------------
__global__ __launch_bounds__(256) void out_kernel(float* __restrict__ out) {
    const int bh = blockIdx.x;
    const int lc = blockIdx.y;
    const int b = bh >> 4, h = bh & 15;

    __shared__ float qs[64][68];
    __shared__ float kvs[64][68];
    __shared__ float sks[64];
    __shared__ float den[64];

    const int tid = threadIdx.x;
    const int tx = tid & 15, ty = tid >> 4;
    const int lr = tid >> 4, lv = tid & 15;

    const float* qb = g_q + ((size_t)b * L_ + lc * 64) * C_ + h * D_;
#pragma unroll
    for (int i = 0; i < 4; i++) {
        const int r = lr + i * 16;
        *(float4*)&qs[r][lv * 4]  = *(const float4*)&qb[(size_t)r * C_ + lv * 4];
        *(float4*)&kvs[r][lv * 4] = *(const float4*)&g_kv[(size_t)bh * D_ * D_ + r * D_ + lv * 4];
    }
    if (tid < 64) sks[tid] = g_sk[bh * D_ + tid];
    __syncthreads();

    if (tid < 64) {
        float s = 0.f;
#pragma unroll 16
        for (int d = 0; d < 64; d++) s += qs[tid][d] * sks[d];
        den[tid] = 1.f / (1e-6f + s);
    }
    __syncthreads();

    float acc[4][4];
#pragma unroll
    for (int i = 0; i < 4; i++)
#pragma unroll
        for (int j = 0; j < 4; j++) acc[i][j] = 0.f;

#pragma unroll 4
    for (int d = 0; d < 64; d++) {
        const float4 kv4 = *(const float4*)&kvs[d][tx * 4];
#pragma unroll
        for (int i = 0; i < 4; i++) {
            const float qv = qs[ty * 4 + i][d];
            acc[i][0] += qv * kv4.x; acc[i][1] += qv * kv4.y;
            acc[i][2] += qv * kv4.z; acc[i][3] += qv * kv4.w;
        }
    }

#pragma unroll
    for (int i = 0; i < 4; i++) {
        const int l = lc * 64 + ty * 4 + i;
        const float dn = den[ty * 4 + i];
        float4 o = make_float4(acc[i][0] * dn, acc[i][1] * dn,
                               acc[i][2] * dn, acc[i][3] * dn);
        *(float4*)&out[((size_t)b * L_ + l) * C_ + h * D_ + tx * 4] = o;
    }
}

// ---------------- launch ----------------------------------------------------
extern "C" void kernel_launch(void* const* d_in, const int* in_sizes, int n_in,
                              void* d_out, int out_size) {
    const float* query   = (const float*)d_in[0];
    const float* key     = (const float*)d_in[1];
    const float* value   = (const float*)d_in[2];
    const float* mask_q  = (const float*)d_in[3];
    const float* mask_kv = (const float*)d_in[4];
    const float* Wq = (const float*)d_in[5];
    const float* bq = (const float*)d_in[6];
    const float* Wk = (const float*)d_in[7];
    const float* bk = (const float*)d_in[8];
    const float* Wv = (const float*)d_in[9];
    const float* bv = (const float*)d_in[10];
    float* out = (float*)d_out;

    static bool attr_done = false;
    if (!attr_done) {
        cudaFuncSetAttribute(proj_h<0>,
            cudaFuncAttributeMaxDynamicSharedMemorySize, PROJ_SMEM);
        cudaFuncSetAttribute(proj_h<1>,
            cudaFuncAttributeMaxDynamicSharedMemorySize, PROJ_SMEM);
        cudaFuncSetAttribute(proj_h<2>,
            cudaFuncAttributeMaxDynamicSharedMemorySize, PROJ_SMEM);
        attr_done = true;
    }

    const int nx4 = MTOT * C_ / 4;   // X elements / 4
    const int nw4 = C_ * C_ / 4;     // W elements / 4
    dim3 pg(C_ / HBN_, MTOT / HBM_); // (8, 128)

    cvt_kernel<0><<<(nx4 + 255) / 256, 256>>>(query, nx4);
    cvt_kernel<1><<<(nw4 + 255) / 256, 256>>>(Wq, nw4);
    proj_h<0><<<pg, 256, PROJ_SMEM>>>(bq, mask_q);

    cvt_kernel<0><<<(nx4 + 255) / 256, 256>>>(key, nx4);
    cvt_kernel<1><<<(nw4 + 255) / 256, 256>>>(Wk, nw4);
    proj_h<1><<<pg, 256, PROJ_SMEM>>>(bk, mask_kv);

    cvt_kernel<0><<<(nx4 + 255) / 256, 256>>>(value, nx4);
    cvt_kernel<1><<<(nw4 + 255) / 256, 256>>>(Wv, nw4);
    proj_h<2><<<pg, 256, PROJ_SMEM>>>(bv, mask_kv);

    kv_kernel<<<dim3(64, 8), 128>>>();
    reduce_kernel<<<64, 256>>>();
    out_kernel<<<dim3(64, 64), 256>>>(out);
}

// round 7
// speedup vs baseline: 2.1695x; 1.0231x over previous
#include <cuda_runtime.h>
#include <cuda_fp16.h>
#include <cstdint>

// Problem constants
#define B_    4
#define L_    4096
#define C_    1024
#define H_    16
#define D_    64
#define MTOT  (B_*L_)      // 16384

// ---------------- scratch (device globals; no allocations allowed) ----------
__device__ __half g_qh[MTOT * C_];         // 32 MB (fp16 intermediates)
__device__ __half g_kh[MTOT * C_];         // 32 MB
__device__ __half g_vh[MTOT * C_];         // 32 MB
__device__ __half g_xh[MTOT * C_];         // 32 MB (fp16 input, reused per proj)
__device__ __half g_wh[C_ * C_];           // 2 MB  (fp16 weight, reused per proj)
__device__ float  g_kvp[64 * 8 * D_ * D_]; // partial kv per (b,h,chunk)
__device__ float  g_skp[64 * 8 * D_];      // partial summed_k
__device__ float  g_kv[64 * D_ * D_];      // reduced kv
__device__ float  g_sk[64 * D_];           // reduced summed_k

// ---------------- helpers ----------------------------------------------------
__device__ __forceinline__ uint32_t f2tf32(float f) {
    uint32_t u;
    asm("cvt.rna.tf32.f32 %0, %1;" : "=r"(u) : "f"(f));
    return u;
}

__device__ __forceinline__ void mma_tf32(float c[4],
        uint32_t a0, uint32_t a1, uint32_t a2, uint32_t a3,
        uint32_t b0, uint32_t b1) {
    asm volatile(
        "mma.sync.aligned.m16n8k8.row.col.f32.tf32.tf32.f32 "
        "{%0,%1,%2,%3}, {%4,%5,%6,%7}, {%8,%9}, {%0,%1,%2,%3};\n"
        : "+f"(c[0]), "+f"(c[1]), "+f"(c[2]), "+f"(c[3])
        : "r"(a0), "r"(a1), "r"(a2), "r"(a3), "r"(b0), "r"(b1));
}

__device__ __forceinline__ void mma_f16(float c[4],
        uint32_t a0, uint32_t a1, uint32_t a2, uint32_t a3,
        uint32_t b0, uint32_t b1) {
    asm volatile(
        "mma.sync.aligned.m16n8k16.row.col.f32.f16.f16.f32 "
        "{%0,%1,%2,%3}, {%4,%5,%6,%7}, {%8,%9}, {%0,%1,%2,%3};\n"
        : "+f"(c[0]), "+f"(c[1]), "+f"(c[2]), "+f"(c[3])
        : "r"(a0), "r"(a1), "r"(a2), "r"(a3), "r"(b0), "r"(b1));
}

__device__ __forceinline__ void cp16(uint32_t saddr, const void* gaddr) {
    asm volatile("cp.async.cg.shared.global [%0], [%1], 16;\n"
                 :: "r"(saddr), "l"(gaddr));
}

__device__ __forceinline__ void ldsm_x4(uint32_t& r0, uint32_t& r1,
                                        uint32_t& r2, uint32_t& r3,
                                        uint32_t addr) {
    asm volatile("ldmatrix.sync.aligned.m8n8.x4.shared.b16 {%0,%1,%2,%3}, [%4];"
                 : "=r"(r0), "=r"(r1), "=r"(r2), "=r"(r3) : "r"(addr));
}

__device__ __forceinline__ void ldsm_x2(uint32_t& r0, uint32_t& r1,
                                        uint32_t addr) {
    asm volatile("ldmatrix.sync.aligned.m8n8.x2.shared.b16 {%0,%1}, [%2];"
                 : "=r"(r0), "=r"(r1) : "r"(addr));
}

#define SW128(off) ((off) ^ ((((uint32_t)(off)) >> 3) & 0x70))

// ---------------- fp32 -> fp16 conversion ------------------------------------
// DST 0: g_xh ; DST 1: g_wh
template <int DST>
__global__ __launch_bounds__(256) void cvt_kernel(
        const float* __restrict__ src, int n4) {
    __half* dst = (DST == 0) ? g_xh : g_wh;
    int i = blockIdx.x * blockDim.x + threadIdx.x;
    if (i < n4) {
        float4 v = ((const float4*)src)[i];
        __half2 h0 = __floats2half2_rn(v.x, v.y);
        __half2 h1 = __floats2half2_rn(v.z, v.w);
        ((__half2*)dst)[2 * i]     = h0;
        ((__half2*)dst)[2 * i + 1] = h1;
    }
}

// ---------------- projection GEMM (fp16 mma): out = X @ W^T + b --------------
// MODE 0: Q (elu+1, *mask) ; MODE 1: K (elu+1, *mask) ; MODE 2: V (*mask)
// 128x128 tile, BK=64 halves (128B rows, SW128), 3-stage cp.async,
// ldmatrix fragment loads, 8 warps (2M x 4N -> 64x32 warp tile).
// Output stored as fp16.
#define HBM_ 128
#define HBN_ 128
#define HBK_ 64                   // halves per k-slab
#define HSTG_BYTES (128 * 128)    // 16 KB per operand per stage
#define HNSTAGE 3
#define HNKT (C_ / HBK_)          // 16
#define PROJ_SMEM (HNSTAGE * 2 * HSTG_BYTES)   // 98304 B

template <int MODE>
__global__ __launch_bounds__(256, 2) void proj_h(
        const float* __restrict__ bias, const float* __restrict__ mask) {
    __half* out = (MODE == 0) ? g_qh : (MODE == 1) ? g_kh : g_vh;
    const __half* __restrict__ Xh = g_xh;
    const __half* __restrict__ Wh = g_wh;

    extern __shared__ char smem[];
    const uint32_t sb = (uint32_t)__cvta_generic_to_shared(smem);
    const int tid  = threadIdx.x;
    const int warp = tid >> 5;
    const int lane = tid & 31;
    const int wm   = warp & 1;    // 2 warps along M (64 rows)
    const int wn   = warp >> 1;   // 4 warps along N (32 cols)
    const int m0   = blockIdx.y * HBM_;
    const int n0   = blockIdx.x * HBN_;

    const int crow = tid >> 1;
    const int cch0 = (tid & 1) * 4;
    const __half* gA = Xh + (size_t)(m0 + crow) * C_ + cch0 * 8;
    const __half* gB = Wh + (size_t)(n0 + crow) * C_ + cch0 * 8;

    auto fill = [&](int stg, int s) {
        const int k0 = s * HBK_;
        const uint32_t sA = sb + (uint32_t)(stg * 2) * HSTG_BYTES;
        const uint32_t sB = sA + HSTG_BYTES;
#pragma unroll
        for (int c = 0; c < 4; c++) {
            const uint32_t off = SW128((uint32_t)(crow * 128 + (cch0 + c) * 16));
            cp16(sA + off, gA + k0 + c * 8);
            cp16(sB + off, gB + k0 + c * 8);
        }
        asm volatile("cp.async.commit_group;\n" ::: "memory");
    };

    float acc[4][4][4];
#pragma unroll
    for (int i = 0; i < 4; i++)
#pragma unroll
        for (int j = 0; j < 4; j++)
#pragma unroll
            for (int r = 0; r < 4; r++) acc[i][j][r] = 0.f;

    const int lm  = lane & 15;
    const int lka = (lane >> 4) * 16;
    const int lnb = lane & 7;
    const int lkb = ((lane >> 3) & 1) * 16;
    uint32_t offA[4], offB[4];
#pragma unroll
    for (int mt = 0; mt < 4; mt++)
        offA[mt] = (uint32_t)((wm * 64 + mt * 16 + lm) * 128 + lka);
#pragma unroll
    for (int nt = 0; nt < 4; nt++)
        offB[nt] = (uint32_t)((wn * 32 + nt * 8 + lnb) * 128 + lkb);

    fill(0, 0);
    fill(1, 1);

    for (int kt = 0; kt < HNKT; kt++) {
        if (kt + 2 < HNKT) {
            fill((kt + 2) % HNSTAGE, kt + 2);
            asm volatile("cp.async.wait_group 2;\n" ::: "memory");
        } else if (kt + 1 < HNKT) {
            asm volatile("cp.async.wait_group 1;\n" ::: "memory");
        } else {
            asm volatile("cp.async.wait_group 0;\n" ::: "memory");
        }
        __syncthreads();

        const int stg = kt % HNSTAGE;
        const uint32_t sA = sb + (uint32_t)(stg * 2) * HSTG_BYTES;
        const uint32_t sB = sA + HSTG_BYTES;

#pragma unroll
        for (int ks = 0; ks < 4; ks++) {
            const uint32_t kb = (uint32_t)(ks * 32);
            uint32_t a[4][4], b[4][2];
#pragma unroll
            for (int mt = 0; mt < 4; mt++)
                ldsm_x4(a[mt][0], a[mt][1], a[mt][2], a[mt][3],
                        sA + SW128(offA[mt] + kb));
#pragma unroll
            for (int nt = 0; nt < 4; nt++)
                ldsm_x2(b[nt][0], b[nt][1], sB + SW128(offB[nt] + kb));
#pragma unroll
            for (int mt = 0; mt < 4; mt++)
#pragma unroll
                for (int nt = 0; nt < 4; nt++)
                    mma_f16(acc[mt][nt], a[mt][0], a[mt][1], a[mt][2], a[mt][3],
                            b[nt][0], b[nt][1]);
        }
        __syncthreads();
    }

    // epilogue: +bias, feature map (Q/K), per-token mask; half2 stores
#pragma unroll
    for (int mt = 0; mt < 4; mt++) {
#pragma unroll
        for (int nt = 0; nt < 4; nt++) {
#pragma unroll
            for (int half_i = 0; half_i < 2; half_i++) {
                const int row = m0 + wm * 64 + mt * 16 + (lane >> 2) + half_i * 8;
                const int col = n0 + wn * 32 + nt * 8 + (lane & 3) * 2;
                float v0 = acc[mt][nt][half_i * 2 + 0] + bias[col + 0];
                float v1 = acc[mt][nt][half_i * 2 + 1] + bias[col + 1];
                if (MODE < 2) {
                    v0 = (v0 > 0.f) ? v0 + 1.f : expf(v0);
                    v1 = (v1 > 0.f) ? v1 + 1.f : expf(v1);
                }
                const float mk = mask[row];
                v0 *= mk; v1 *= mk;
                *(__half2*)&out[(size_t)row * C_ + col] = __floats2half2_rn(v0, v1);
            }
        }
    }
}

// ---------------- phase 2: partial kv = K^T V via tf32 mma ------------------
// Inputs now fp16; loader converts to fp32 smem. Compute loop unchanged.
#define KSTR 72

__global__ __launch_bounds__(128) void kv_kernel() {
    const int bh = blockIdx.x;
    const int ch = blockIdx.y;
    const int b = bh >> 4, h = bh & 15;

    __shared__ float Ks[64][KSTR];
    __shared__ float Vs[64][KSTR];

    const int tid  = threadIdx.x;
    const int warp = tid >> 5;
    const int lane = tid & 31;
    const int gid  = lane >> 2;
    const int tig  = lane & 3;

    const size_t base = ((size_t)b * L_ + ch * 512) * C_ + h * D_;
    const __half* kb = g_kh + base;
    const __half* vb = g_vh + base;

    float acc[4][2][4];
#pragma unroll
    for (int i = 0; i < 4; i++)
#pragma unroll
        for (int j = 0; j < 2; j++)
#pragma unroll
            for (int r = 0; r < 4; r++) acc[i][j][r] = 0.f;
    float sk = 0.f;

    for (int t0 = 0; t0 < 512; t0 += 64) {
#pragma unroll
        for (int i = 0; i < 8; i++) {
            const int idx = tid + i * 128;
            const int r = idx >> 4, c = (idx & 15) * 4;
            const __half2* kp = (const __half2*)&kb[(size_t)(t0 + r) * C_ + c];
            const __half2* vp = (const __half2*)&vb[(size_t)(t0 + r) * C_ + c];
            float2 k0 = __half22float2(kp[0]), k1 = __half22float2(kp[1]);
            float2 v0 = __half22float2(vp[0]), v1 = __half22float2(vp[1]);
            Ks[r][c + 0] = k0.x; Ks[r][c + 1] = k0.y;
            Ks[r][c + 2] = k1.x; Ks[r][c + 3] = k1.y;
            Vs[r][c + 0] = v0.x; Vs[r][c + 1] = v0.y;
            Vs[r][c + 2] = v1.x; Vs[r][c + 3] = v1.y;
        }
        __syncthreads();

        if (tid < 64) {
#pragma unroll 8
            for (int l = 0; l < 64; l++) sk += Ks[l][tid];
        }

#pragma unroll
        for (int kk = 0; kk < 64; kk += 8) {
            uint32_t a[4][4], bfr[2][2];
#pragma unroll
            for (int mt = 0; mt < 4; mt++) {
                const int r0 = mt * 16;
                a[mt][0] = f2tf32(Ks[kk + tig    ][r0 + gid    ]);
                a[mt][1] = f2tf32(Ks[kk + tig    ][r0 + gid + 8]);
                a[mt][2] = f2tf32(Ks[kk + tig + 4][r0 + gid    ]);
                a[mt][3] = f2tf32(Ks[kk + tig + 4][r0 + gid + 8]);
            }
#pragma unroll
            for (int nt = 0; nt < 2; nt++) {
                const int c0 = warp * 16 + nt * 8;
                bfr[nt][0] = f2tf32(Vs[kk + tig    ][c0 + gid]);
                bfr[nt][1] = f2tf32(Vs[kk + tig + 4][c0 + gid]);
            }
#pragma unroll
            for (int mt = 0; mt < 4; mt++)
#pragma unroll
                for (int nt = 0; nt < 2; nt++)
                    mma_tf32(acc[mt][nt], a[mt][0], a[mt][1], a[mt][2], a[mt][3],
                             bfr[nt][0], bfr[nt][1]);
        }
        __syncthreads();
    }

    float* outp = g_kvp + (size_t)(bh * 8 + ch) * D_ * D_;
#pragma unroll
    for (int mt = 0; mt < 4; mt++) {
#pragma unroll
        for (int nt = 0; nt < 2; nt++) {
#pragma unroll
            for (int half_i = 0; half_i < 2; half_i++) {
                const int d = mt * 16 + gid + half_i * 8;
                const int e = warp * 16 + nt * 8 + tig * 2;
                float2 o = make_float2(acc[mt][nt][half_i * 2 + 0],
                                       acc[mt][nt][half_i * 2 + 1]);
                *(float2*)&outp[d * D_ + e] = o;
            }
        }
    }
    if (tid < 64) g_skp[(bh * 8 + ch) * D_ + tid] = sk;
}

// ---------------- phase 2b: reduce chunk partials ---------------------------
__global__ __launch_bounds__(256) void reduce_kernel() {
    const int bh = blockIdx.x;
    const int tid = threadIdx.x;
    for (int idx = tid; idx < D_ * D_; idx += 256) {
        float s = 0.f;
#pragma unroll
        for (int c = 0; c < 8; c++) s += g_kvp[(size_t)(bh * 8 + c) * D_ * D_ + idx];
        g_kv[(size_t)bh * D_ * D_ + idx] = s;
    }
    if (tid < 64) {
        float s = 0.f;
#pragma unroll
        for (int c = 0; c < 8; c++) s += g_skp[(bh * 8 + c) * D_ + tid];
        g_sk[bh * D_ + tid] = s;
    }
}

// ---------------- phase 3: out = (q @ kv) * denom ---------------------------
__global__ __launch_bounds__(256) void out_kernel(float* __restrict__ out) {
    const int bh = blockIdx.x;
    const int lc = blockIdx.y;
    const int b = bh >> 4, h = bh & 15;

    __shared__ float qs[64][68];
    __shared__ float kvs[64][68];
    __shared__ float sks[64];
    __shared__ float den[64];

    const int tid = threadIdx.x;
    const int tx = tid & 15, ty = tid >> 4;
    const int lr = tid >> 4, lv = tid & 15;

    const __half* qb = g_qh + ((size_t)b * L_ + lc * 64) * C_ + h * D_;
#pragma unroll
    for (int i = 0; i < 4; i++) {
        const int r = lr + i * 16;
        const __half2* qp = (const __half2*)&qb[(size_t)r * C_ + lv * 4];
        float2 q0 = __half22float2(qp[0]), q1 = __half22float2(qp[1]);
        qs[r][lv * 4 + 0] = q0.x; qs[r][lv * 4 + 1] = q0.y;
        qs[r][lv * 4 + 2] = q1.x; qs[r][lv * 4 + 3] = q1.y;
        *(float4*)&kvs[r][lv * 4] = *(const float4*)&g_kv[(size_t)bh * D_ * D_ + r * D_ + lv * 4];
    }
    if (tid < 64) sks[tid] = g_sk[bh * D_ + tid];
    __syncthreads();

    if (tid < 64) {
        float s = 0.f;
#pragma unroll 16
        for (int d = 0; d < 64; d++) s += qs[tid][d] * sks[d];
        den[tid] = 1.f / (1e-6f + s);
    }
    __syncthreads();

    float acc[4][4];
#pragma unroll
    for (int i = 0; i < 4; i++)
#pragma unroll
        for (int j = 0; j < 4; j++) acc[i][j] = 0.f;

#pragma unroll 4
    for (int d = 0; d < 64; d++) {
        const float4 kv4 = *(const float4*)&kvs[d][tx * 4];
#pragma unroll
        for (int i = 0; i < 4; i++) {
            const float qv = qs[ty * 4 + i][d];
            acc[i][0] += qv * kv4.x; acc[i][1] += qv * kv4.y;
            acc[i][2] += qv * kv4.z; acc[i][3] += qv * kv4.w;
        }
    }

#pragma unroll
    for (int i = 0; i < 4; i++) {
        const int l = lc * 64 + ty * 4 + i;
        const float dn = den[ty * 4 + i];
        float4 o = make_float4(acc[i][0] * dn, acc[i][1] * dn,
                               acc[i][2] * dn, acc[i][3] * dn);
        *(float4*)&out[((size_t)b * L_ + l) * C_ + h * D_ + tx * 4] = o;
    }
}

// ---------------- launch ----------------------------------------------------
extern "C" void kernel_launch(void* const* d_in, const int* in_sizes, int n_in,
                              void* d_out, int out_size) {
    const float* query   = (const float*)d_in[0];
    const float* key     = (const float*)d_in[1];
    const float* value   = (const float*)d_in[2];
    const float* mask_q  = (const float*)d_in[3];
    const float* mask_kv = (const float*)d_in[4];
    const float* Wq = (const float*)d_in[5];
    const float* bq = (const float*)d_in[6];
    const float* Wk = (const float*)d_in[7];
    const float* bk = (const float*)d_in[8];
    const float* Wv = (const float*)d_in[9];
    const float* bv = (const float*)d_in[10];
    float* out = (float*)d_out;

    static bool attr_done = false;
    if (!attr_done) {
        cudaFuncSetAttribute(proj_h<0>,
            cudaFuncAttributeMaxDynamicSharedMemorySize, PROJ_SMEM);
        cudaFuncSetAttribute(proj_h<1>,
            cudaFuncAttributeMaxDynamicSharedMemorySize, PROJ_SMEM);
        cudaFuncSetAttribute(proj_h<2>,
            cudaFuncAttributeMaxDynamicSharedMemorySize, PROJ_SMEM);
        attr_done = true;
    }

    const int nx4 = MTOT * C_ / 4;
    const int nw4 = C_ * C_ / 4;
    dim3 pg(C_ / HBN_, MTOT / HBM_); // (8, 128)

    cvt_kernel<0><<<(nx4 + 255) / 256, 256>>>(query, nx4);
    cvt_kernel<1><<<(nw4 + 255) / 256, 256>>>(Wq, nw4);
    proj_h<0><<<pg, 256, PROJ_SMEM>>>(bq, mask_q);

    cvt_kernel<0><<<(nx4 + 255) / 256, 256>>>(key, nx4);
    cvt_kernel<1><<<(nw4 + 255) / 256, 256>>>(Wk, nw4);
    proj_h<1><<<pg, 256, PROJ_SMEM>>>(bk, mask_kv);

    cvt_kernel<0><<<(nx4 + 255) / 256, 256>>>(value, nx4);
    cvt_kernel<1><<<(nw4 + 255) / 256, 256>>>(Wv, nw4);
    proj_h<2><<<pg, 256, PROJ_SMEM>>>(bv, mask_kv);

    kv_kernel<<<dim3(64, 8), 128>>>();
    reduce_kernel<<<64, 256>>>();
    out_kernel<<<dim3(64, 64), 256>>>(out);
}

// round 8
// speedup vs baseline: 2.2486x; 1.0365x over previous
#include <cuda_runtime.h>
#include <cuda_fp16.h>
#include <cstdint>

// Problem constants
#define B_    4
#define L_    4096
#define C_    1024
#define H_    16
#define D_    64
#define MTOT  (B_*L_)      // 16384

// ---------------- scratch (device globals; no allocations allowed) ----------
__device__ __half g_qh[MTOT * C_];         // 32 MB (fp16 intermediates)
__device__ __half g_kh[MTOT * C_];         // 32 MB
__device__ __half g_vh[MTOT * C_];         // 32 MB
__device__ __half g_xq[MTOT * C_];         // 32 MB fp16 inputs
__device__ __half g_xk[MTOT * C_];         // 32 MB
__device__ __half g_xv[MTOT * C_];         // 32 MB
__device__ __half g_wq[C_ * C_];           // 2 MB fp16 weights
__device__ __half g_wk[C_ * C_];
__device__ __half g_wv[C_ * C_];
__device__ float  g_kvp[64 * 8 * D_ * D_]; // partial kv per (b,h,chunk)
__device__ float  g_skp[64 * 8 * D_];      // partial summed_k
__device__ float  g_kv[64 * D_ * D_];      // reduced kv
__device__ float  g_sk[64 * D_];           // reduced summed_k

// ---------------- helpers ----------------------------------------------------
__device__ __forceinline__ void mma_f16(float c[4],
        uint32_t a0, uint32_t a1, uint32_t a2, uint32_t a3,
        uint32_t b0, uint32_t b1) {
    asm volatile(
        "mma.sync.aligned.m16n8k16.row.col.f32.f16.f16.f32 "
        "{%0,%1,%2,%3}, {%4,%5,%6,%7}, {%8,%9}, {%0,%1,%2,%3};\n"
        : "+f"(c[0]), "+f"(c[1]), "+f"(c[2]), "+f"(c[3])
        : "r"(a0), "r"(a1), "r"(a2), "r"(a3), "r"(b0), "r"(b1));
}

__device__ __forceinline__ void cp16(uint32_t saddr, const void* gaddr) {
    asm volatile("cp.async.cg.shared.global [%0], [%1], 16;\n"
                 :: "r"(saddr), "l"(gaddr));
}

__device__ __forceinline__ void ldsm_x4(uint32_t& r0, uint32_t& r1,
                                        uint32_t& r2, uint32_t& r3,
                                        uint32_t addr) {
    asm volatile("ldmatrix.sync.aligned.m8n8.x4.shared.b16 {%0,%1,%2,%3}, [%4];"
                 : "=r"(r0), "=r"(r1), "=r"(r2), "=r"(r3) : "r"(addr));
}

__device__ __forceinline__ void ldsm_x2(uint32_t& r0, uint32_t& r1,
                                        uint32_t addr) {
    asm volatile("ldmatrix.sync.aligned.m8n8.x2.shared.b16 {%0,%1}, [%2];"
                 : "=r"(r0), "=r"(r1) : "r"(addr));
}

__device__ __forceinline__ void ldsm_x4_t(uint32_t& r0, uint32_t& r1,
                                          uint32_t& r2, uint32_t& r3,
                                          uint32_t addr) {
    asm volatile("ldmatrix.sync.aligned.m8n8.x4.trans.shared.b16 {%0,%1,%2,%3}, [%4];"
                 : "=r"(r0), "=r"(r1), "=r"(r2), "=r"(r3) : "r"(addr));
}

__device__ __forceinline__ void ldsm_x2_t(uint32_t& r0, uint32_t& r1,
                                          uint32_t addr) {
    asm volatile("ldmatrix.sync.aligned.m8n8.x2.trans.shared.b16 {%0,%1}, [%2];"
                 : "=r"(r0), "=r"(r1) : "r"(addr));
}

#define SW128(off) ((off) ^ ((((uint32_t)(off)) >> 3) & 0x70))

// ---------------- fp32 -> fp16 conversions (consolidated) --------------------
// X: blockIdx.y selects query/key/value; 2 float4 per thread.
__global__ __launch_bounds__(256) void cvt_x3(
        const float* __restrict__ q, const float* __restrict__ k,
        const float* __restrict__ v) {
    const float* src = (blockIdx.y == 0) ? q : (blockIdx.y == 1) ? k : v;
    __half* dst = (blockIdx.y == 0) ? g_xq : (blockIdx.y == 1) ? g_xk : g_xv;
    const int i = blockIdx.x * 256 + threadIdx.x;   // 0 .. MTOT*C_/8-1
    const float4 v0 = ((const float4*)src)[2 * i];
    const float4 v1 = ((const float4*)src)[2 * i + 1];
    __half2 h0 = __floats2half2_rn(v0.x, v0.y);
    __half2 h1 = __floats2half2_rn(v0.z, v0.w);
    __half2 h2 = __floats2half2_rn(v1.x, v1.y);
    __half2 h3 = __floats2half2_rn(v1.z, v1.w);
    uint4 o;
    o.x = *(uint32_t*)&h0; o.y = *(uint32_t*)&h1;
    o.z = *(uint32_t*)&h2; o.w = *(uint32_t*)&h3;
    *(uint4*)&dst[8 * (size_t)i] = o;
}

__global__ __launch_bounds__(256) void cvt_w3(
        const float* __restrict__ wq, const float* __restrict__ wk,
        const float* __restrict__ wv) {
    const float* src = (blockIdx.y == 0) ? wq : (blockIdx.y == 1) ? wk : wv;
    __half* dst = (blockIdx.y == 0) ? g_wq : (blockIdx.y == 1) ? g_wk : g_wv;
    const int i = blockIdx.x * 256 + threadIdx.x;   // 0 .. C_*C_/8-1
    const float4 v0 = ((const float4*)src)[2 * i];
    const float4 v1 = ((const float4*)src)[2 * i + 1];
    __half2 h0 = __floats2half2_rn(v0.x, v0.y);
    __half2 h1 = __floats2half2_rn(v0.z, v0.w);
    __half2 h2 = __floats2half2_rn(v1.x, v1.y);
    __half2 h3 = __floats2half2_rn(v1.z, v1.w);
    uint4 o;
    o.x = *(uint32_t*)&h0; o.y = *(uint32_t*)&h1;
    o.z = *(uint32_t*)&h2; o.w = *(uint32_t*)&h3;
    *(uint4*)&dst[8 * (size_t)i] = o;
}

// ---------------- projection GEMM (fp16 mma): out = X @ W^T + b --------------
// MODE 0: Q (elu+1, *mask) ; MODE 1: K (elu+1, *mask) ; MODE 2: V (*mask)
#define HBM_ 128
#define HBN_ 128
#define HBK_ 64                   // halves per k-slab
#define HSTG_BYTES (128 * 128)    // 16 KB per operand per stage
#define HNSTAGE 3
#define HNKT (C_ / HBK_)          // 16
#define PROJ_SMEM (HNSTAGE * 2 * HSTG_BYTES)   // 98304 B

template <int MODE>
__global__ __launch_bounds__(256, 2) void proj_h(
        const float* __restrict__ bias, const float* __restrict__ mask) {
    __half* out = (MODE == 0) ? g_qh : (MODE == 1) ? g_kh : g_vh;
    const __half* __restrict__ Xh = (MODE == 0) ? g_xq : (MODE == 1) ? g_xk : g_xv;
    const __half* __restrict__ Wh = (MODE == 0) ? g_wq : (MODE == 1) ? g_wk : g_wv;

    extern __shared__ char smem[];
    const uint32_t sb = (uint32_t)__cvta_generic_to_shared(smem);
    const int tid  = threadIdx.x;
    const int warp = tid >> 5;
    const int lane = tid & 31;
    const int wm   = warp & 1;    // 2 warps along M (64 rows)
    const int wn   = warp >> 1;   // 4 warps along N (32 cols)
    const int m0   = blockIdx.y * HBM_;
    const int n0   = blockIdx.x * HBN_;

    const int crow = tid >> 1;
    const int cch0 = (tid & 1) * 4;
    const __half* gA = Xh + (size_t)(m0 + crow) * C_ + cch0 * 8;
    const __half* gB = Wh + (size_t)(n0 + crow) * C_ + cch0 * 8;

    auto fill = [&](int stg, int s) {
        const int k0 = s * HBK_;
        const uint32_t sA = sb + (uint32_t)(stg * 2) * HSTG_BYTES;
        const uint32_t sB = sA + HSTG_BYTES;
#pragma unroll
        for (int c = 0; c < 4; c++) {
            const uint32_t off = SW128((uint32_t)(crow * 128 + (cch0 + c) * 16));
            cp16(sA + off, gA + k0 + c * 8);
            cp16(sB + off, gB + k0 + c * 8);
        }
        asm volatile("cp.async.commit_group;\n" ::: "memory");
    };

    float acc[4][4][4];
#pragma unroll
    for (int i = 0; i < 4; i++)
#pragma unroll
        for (int j = 0; j < 4; j++)
#pragma unroll
            for (int r = 0; r < 4; r++) acc[i][j][r] = 0.f;

    const int lm  = lane & 15;
    const int lka = (lane >> 4) * 16;
    const int lnb = lane & 7;
    const int lkb = ((lane >> 3) & 1) * 16;
    uint32_t offA[4], offB[4];
#pragma unroll
    for (int mt = 0; mt < 4; mt++)
        offA[mt] = (uint32_t)((wm * 64 + mt * 16 + lm) * 128 + lka);
#pragma unroll
    for (int nt = 0; nt < 4; nt++)
        offB[nt] = (uint32_t)((wn * 32 + nt * 8 + lnb) * 128 + lkb);

    fill(0, 0);
    fill(1, 1);

    for (int kt = 0; kt < HNKT; kt++) {
        if (kt + 2 < HNKT) {
            fill((kt + 2) % HNSTAGE, kt + 2);
            asm volatile("cp.async.wait_group 2;\n" ::: "memory");
        } else if (kt + 1 < HNKT) {
            asm volatile("cp.async.wait_group 1;\n" ::: "memory");
        } else {
            asm volatile("cp.async.wait_group 0;\n" ::: "memory");
        }
        __syncthreads();

        const int stg = kt % HNSTAGE;
        const uint32_t sA = sb + (uint32_t)(stg * 2) * HSTG_BYTES;
        const uint32_t sB = sA + HSTG_BYTES;

#pragma unroll
        for (int ks = 0; ks < 4; ks++) {
            const uint32_t kb = (uint32_t)(ks * 32);
            uint32_t a[4][4], b[4][2];
#pragma unroll
            for (int mt = 0; mt < 4; mt++)
                ldsm_x4(a[mt][0], a[mt][1], a[mt][2], a[mt][3],
                        sA + SW128(offA[mt] + kb));
#pragma unroll
            for (int nt = 0; nt < 4; nt++)
                ldsm_x2(b[nt][0], b[nt][1], sB + SW128(offB[nt] + kb));
#pragma unroll
            for (int mt = 0; mt < 4; mt++)
#pragma unroll
                for (int nt = 0; nt < 4; nt++)
                    mma_f16(acc[mt][nt], a[mt][0], a[mt][1], a[mt][2], a[mt][3],
                            b[nt][0], b[nt][1]);
        }
        __syncthreads();
    }

    // epilogue: +bias, feature map (Q/K), per-token mask; half2 stores
#pragma unroll
    for (int mt = 0; mt < 4; mt++) {
#pragma unroll
        for (int nt = 0; nt < 4; nt++) {
#pragma unroll
            for (int half_i = 0; half_i < 2; half_i++) {
                const int row = m0 + wm * 64 + mt * 16 + (lane >> 2) + half_i * 8;
                const int col = n0 + wn * 32 + nt * 8 + (lane & 3) * 2;
                float v0 = acc[mt][nt][half_i * 2 + 0] + bias[col + 0];
                float v1 = acc[mt][nt][half_i * 2 + 1] + bias[col + 1];
                if (MODE < 2) {
                    v0 = (v0 > 0.f) ? v0 + 1.f : expf(v0);
                    v1 = (v1 > 0.f) ? v1 + 1.f : expf(v1);
                }
                const float mk = mask[row];
                v0 *= mk; v1 *= mk;
                *(__half2*)&out[(size_t)row * C_ + col] = __floats2half2_rn(v0, v1);
            }
        }
    }
}

// ---------------- phase 2: partial kv = K^T V via fp16 mma ------------------
// kv[d][e] = sum_l K[l][d] * V[l][e]. A/B from ldmatrix.trans on [l][*] smem.
#define KVSTR 72   // halves per row: 144B = 9*16B (aligned, conflict-free)

__global__ __launch_bounds__(128) void kv_kernel() {
    const int bh = blockIdx.x;   // b*16+h
    const int ch = blockIdx.y;   // L chunk of 512
    const int b = bh >> 4, h = bh & 15;

    __shared__ __half Ks[64][KVSTR];
    __shared__ __half Vs[64][KVSTR];

    const int tid  = threadIdx.x;
    const int warp = tid >> 5;
    const int lane = tid & 31;
    const int gid  = lane >> 2;
    const int tig  = lane & 3;

    const size_t base = ((size_t)b * L_ + ch * 512) * C_ + h * D_;
    const __half* kb = g_kh + base;
    const __half* vb = g_vh + base;

    float acc[4][2][4];
#pragma unroll
    for (int i = 0; i < 4; i++)
#pragma unroll
        for (int j = 0; j < 2; j++)
#pragma unroll
            for (int r = 0; r < 4; r++) acc[i][j][r] = 0.f;
    float sk = 0.f;

    // ldmatrix.trans per-thread source addresses (relative to kk/d-base)
    const int ti   = lane & 7;
    const int tsel = lane >> 3;
    const int arow_off = ((tsel & 2) ? 8 : 0) + ti;   // + kk
    const int acol_off = ((tsel & 1) ? 8 : 0);        // + mt*16
    const int brow_off = ((tsel & 1) ? 8 : 0) + ti;   // + kk (x2: threads 0-15)

    for (int t0 = 0; t0 < 512; t0 += 64) {
        // load 64 tokens x 64 halves of K and V (16B chunks)
#pragma unroll
        for (int i = 0; i < 4; i++) {
            const int c = tid + i * 128;          // chunk 0..511
            const int r = c >> 3, co = (c & 7) * 8;
            *(uint4*)&Ks[r][co] = *(const uint4*)&kb[(size_t)(t0 + r) * C_ + co];
            *(uint4*)&Vs[r][co] = *(const uint4*)&vb[(size_t)(t0 + r) * C_ + co];
        }
        __syncthreads();

        if (tid < 64) {
#pragma unroll 8
            for (int l = 0; l < 64; l++) sk += __half2float(Ks[l][tid]);
        }

#pragma unroll
        for (int kk = 0; kk < 64; kk += 16) {
            uint32_t a[4][4], bfr[2][2];
#pragma unroll
            for (int mt = 0; mt < 4; mt++) {
                const uint32_t addr = (uint32_t)__cvta_generic_to_shared(
                    &Ks[kk + arow_off][mt * 16 + acol_off]);
                ldsm_x4_t(a[mt][0], a[mt][1], a[mt][2], a[mt][3], addr);
            }
#pragma unroll
            for (int nt = 0; nt < 2; nt++) {
                const uint32_t addr = (uint32_t)__cvta_generic_to_shared(
                    &Vs[kk + brow_off][warp * 16 + nt * 8]);
                ldsm_x2_t(bfr[nt][0], bfr[nt][1], addr);
            }
#pragma unroll
            for (int mt = 0; mt < 4; mt++)
#pragma unroll
                for (int nt = 0; nt < 2; nt++)
                    mma_f16(acc[mt][nt], a[mt][0], a[mt][1], a[mt][2], a[mt][3],
                            bfr[nt][0], bfr[nt][1]);
        }
        __syncthreads();
    }

    float* outp = g_kvp + (size_t)(bh * 8 + ch) * D_ * D_;
#pragma unroll
    for (int mt = 0; mt < 4; mt++) {
#pragma unroll
        for (int nt = 0; nt < 2; nt++) {
#pragma unroll
            for (int half_i = 0; half_i < 2; half_i++) {
                const int d = mt * 16 + gid + half_i * 8;
                const int e = warp * 16 + nt * 8 + tig * 2;
                float2 o = make_float2(acc[mt][nt][half_i * 2 + 0],
                                       acc[mt][nt][half_i * 2 + 1]);
                *(float2*)&outp[d * D_ + e] = o;
            }
        }
    }
    if (tid < 64) g_skp[(bh * 8 + ch) * D_ + tid] = sk;
}

// ---------------- phase 2b: reduce chunk partials ---------------------------
__global__ __launch_bounds__(256) void reduce_kernel() {
    const int bh = blockIdx.x;
    const int tid = threadIdx.x;
    for (int idx = tid; idx < D_ * D_; idx += 256) {
        float s = 0.f;
#pragma unroll
        for (int c = 0; c < 8; c++) s += g_kvp[(size_t)(bh * 8 + c) * D_ * D_ + idx];
        g_kv[(size_t)bh * D_ * D_ + idx] = s;
    }
    if (tid < 64) {
        float s = 0.f;
#pragma unroll
        for (int c = 0; c < 8; c++) s += g_skp[(bh * 8 + c) * D_ + tid];
        g_sk[bh * D_ + tid] = s;
    }
}

// ---------------- phase 3: out = (q @ kv) * denom ---------------------------
__global__ __launch_bounds__(256) void out_kernel(float* __restrict__ out) {
    const int bh = blockIdx.x;
    const int lc = blockIdx.y;
    const int b = bh >> 4, h = bh & 15;

    __shared__ float qs[64][68];
    __shared__ float kvs[64][68];
    __shared__ float sks[64];
    __shared__ float den[64];

    const int tid = threadIdx.x;
    const int tx = tid & 15, ty = tid >> 4;
    const int lr = tid >> 4, lv = tid & 15;

    const __half* qb = g_qh + ((size_t)b * L_ + lc * 64) * C_ + h * D_;
#pragma unroll
    for (int i = 0; i < 4; i++) {
        const int r = lr + i * 16;
        const __half2* qp = (const __half2*)&qb[(size_t)r * C_ + lv * 4];
        float2 q0 = __half22float2(qp[0]), q1 = __half22float2(qp[1]);
        qs[r][lv * 4 + 0] = q0.x; qs[r][lv * 4 + 1] = q0.y;
        qs[r][lv * 4 + 2] = q1.x; qs[r][lv * 4 + 3] = q1.y;
        *(float4*)&kvs[r][lv * 4] = *(const float4*)&g_kv[(size_t)bh * D_ * D_ + r * D_ + lv * 4];
    }
    if (tid < 64) sks[tid] = g_sk[bh * D_ + tid];
    __syncthreads();

    if (tid < 64) {
        float s = 0.f;
#pragma unroll 16
        for (int d = 0; d < 64; d++) s += qs[tid][d] * sks[d];
        den[tid] = 1.f / (1e-6f + s);
    }
    __syncthreads();

    float acc[4][4];
#pragma unroll
    for (int i = 0; i < 4; i++)
#pragma unroll
        for (int j = 0; j < 4; j++) acc[i][j] = 0.f;

#pragma unroll 4
    for (int d = 0; d < 64; d++) {
        const float4 kv4 = *(const float4*)&kvs[d][tx * 4];
#pragma unroll
        for (int i = 0; i < 4; i++) {
            const float qv = qs[ty * 4 + i][d];
            acc[i][0] += qv * kv4.x; acc[i][1] += qv * kv4.y;
            acc[i][2] += qv * kv4.z; acc[i][3] += qv * kv4.w;
        }
    }

#pragma unroll
    for (int i = 0; i < 4; i++) {
        const int l = lc * 64 + ty * 4 + i;
        const float dn = den[ty * 4 + i];
        float4 o = make_float4(acc[i][0] * dn, acc[i][1] * dn,
                               acc[i][2] * dn, acc[i][3] * dn);
        *(float4*)&out[((size_t)b * L_ + l) * C_ + h * D_ + tx * 4] = o;
    }
}

// ---------------- launch ----------------------------------------------------
extern "C" void kernel_launch(void* const* d_in, const int* in_sizes, int n_in,
                              void* d_out, int out_size) {
    const float* query   = (const float*)d_in[0];
    const float* key     = (const float*)d_in[1];
    const float* value   = (const float*)d_in[2];
    const float* mask_q  = (const float*)d_in[3];
    const float* mask_kv = (const float*)d_in[4];
    const float* Wq = (const float*)d_in[5];
    const float* bq = (const float*)d_in[6];
    const float* Wk = (const float*)d_in[7];
    const float* bk = (const float*)d_in[8];
    const float* Wv = (const float*)d_in[9];
    const float* bv = (const float*)d_in[10];
    float* out = (float*)d_out;

    static bool attr_done = false;
    if (!attr_done) {
        cudaFuncSetAttribute(proj_h<0>,
            cudaFuncAttributeMaxDynamicSharedMemorySize, PROJ_SMEM);
        cudaFuncSetAttribute(proj_h<1>,
            cudaFuncAttributeMaxDynamicSharedMemorySize, PROJ_SMEM);
        cudaFuncSetAttribute(proj_h<2>,
            cudaFuncAttributeMaxDynamicSharedMemorySize, PROJ_SMEM);
        attr_done = true;
    }

    dim3 pg(C_ / HBN_, MTOT / HBM_);           // (8, 128)
    dim3 cx(MTOT * C_ / 8 / 256, 3);           // (8192, 3)
    dim3 cw(C_ * C_ / 8 / 256, 3);             // (512, 3)

    cvt_x3<<<cx, 256>>>(query, key, value);
    cvt_w3<<<cw, 256>>>(Wq, Wk, Wv);

    proj_h<0><<<pg, 256, PROJ_SMEM>>>(bq, mask_q);
    proj_h<1><<<pg, 256, PROJ_SMEM>>>(bk, mask_kv);
    proj_h<2><<<pg, 256, PROJ_SMEM>>>(bv, mask_kv);

    kv_kernel<<<dim3(64, 8), 128>>>();
    reduce_kernel<<<64, 256>>>();
    out_kernel<<<dim3(64, 64), 256>>>(out);
}

// round 10
// speedup vs baseline: 2.4322x; 1.0816x over previous
#include <cuda_runtime.h>
#include <cuda_fp16.h>
#include <cstdint>

// Problem constants
#define B_    4
#define L_    4096
#define C_    1024
#define H_    16
#define D_    64
#define MTOT  (B_*L_)      // 16384

// ---------------- scratch (device globals; no allocations allowed) ----------
__device__ __half g_qh[MTOT * C_];         // 32 MB (fp16 intermediates)
__device__ __half g_kh[MTOT * C_];         // 32 MB
__device__ __half g_vh[MTOT * C_];         // 32 MB
__device__ __half g_xq[MTOT * C_];         // 32 MB fp16 inputs
__device__ __half g_xk[MTOT * C_];         // 32 MB
__device__ __half g_xv[MTOT * C_];         // 32 MB
__device__ __half g_wq[C_ * C_];           // 2 MB fp16 weights
__device__ __half g_wk[C_ * C_];
__device__ __half g_wv[C_ * C_];
__device__ float  g_kvp[64 * 8 * D_ * D_]; // partial kv per (b,h,chunk)
__device__ float  g_skp[64 * 8 * D_];      // partial summed_k
__device__ float  g_kv[64 * D_ * D_];      // reduced kv
__device__ float  g_sk[64 * D_];           // reduced summed_k

// ---------------- helpers ----------------------------------------------------
__device__ __forceinline__ void mma_f16(float c[4],
        uint32_t a0, uint32_t a1, uint32_t a2, uint32_t a3,
        uint32_t b0, uint32_t b1) {
    asm volatile(
        "mma.sync.aligned.m16n8k16.row.col.f32.f16.f16.f32 "
        "{%0,%1,%2,%3}, {%4,%5,%6,%7}, {%8,%9}, {%0,%1,%2,%3};\n"
        : "+f"(c[0]), "+f"(c[1]), "+f"(c[2]), "+f"(c[3])
        : "r"(a0), "r"(a1), "r"(a2), "r"(a3), "r"(b0), "r"(b1));
}

__device__ __forceinline__ void cp16(uint32_t saddr, const void* gaddr) {
    asm volatile("cp.async.cg.shared.global [%0], [%1], 16;\n"
                 :: "r"(saddr), "l"(gaddr));
}

__device__ __forceinline__ void ldsm_x4(uint32_t& r0, uint32_t& r1,
                                        uint32_t& r2, uint32_t& r3,
                                        uint32_t addr) {
    asm volatile("ldmatrix.sync.aligned.m8n8.x4.shared.b16 {%0,%1,%2,%3}, [%4];"
                 : "=r"(r0), "=r"(r1), "=r"(r2), "=r"(r3) : "r"(addr));
}

__device__ __forceinline__ void ldsm_x4_t(uint32_t& r0, uint32_t& r1,
                                          uint32_t& r2, uint32_t& r3,
                                          uint32_t addr) {
    asm volatile("ldmatrix.sync.aligned.m8n8.x4.trans.shared.b16 {%0,%1,%2,%3}, [%4];"
                 : "=r"(r0), "=r"(r1), "=r"(r2), "=r"(r3) : "r"(addr));
}

__device__ __forceinline__ void ldsm_x2_t(uint32_t& r0, uint32_t& r1,
                                          uint32_t addr) {
    asm volatile("ldmatrix.sync.aligned.m8n8.x2.trans.shared.b16 {%0,%1}, [%2];"
                 : "=r"(r0), "=r"(r1) : "r"(addr));
}

#define SW128(off) ((off) ^ ((((uint32_t)(off)) >> 3) & 0x70))

// ---------------- fp32 -> fp16 conversions (consolidated) --------------------
__global__ __launch_bounds__(256) void cvt_x3(
        const float* __restrict__ q, const float* __restrict__ k,
        const float* __restrict__ v) {
    const float* src = (blockIdx.y == 0) ? q : (blockIdx.y == 1) ? k : v;
    __half* dst = (blockIdx.y == 0) ? g_xq : (blockIdx.y == 1) ? g_xk : g_xv;
    const int i = blockIdx.x * 256 + threadIdx.x;
    const float4 v0 = ((const float4*)src)[2 * i];
    const float4 v1 = ((const float4*)src)[2 * i + 1];
    __half2 h0 = __floats2half2_rn(v0.x, v0.y);
    __half2 h1 = __floats2half2_rn(v0.z, v0.w);
    __half2 h2 = __floats2half2_rn(v1.x, v1.y);
    __half2 h3 = __floats2half2_rn(v1.z, v1.w);
    uint4 o;
    o.x = *(uint32_t*)&h0; o.y = *(uint32_t*)&h1;
    o.z = *(uint32_t*)&h2; o.w = *(uint32_t*)&h3;
    *(uint4*)&dst[8 * (size_t)i] = o;
}

__global__ __launch_bounds__(256) void cvt_w3(
        const float* __restrict__ wq, const float* __restrict__ wk,
        const float* __restrict__ wv) {
    const float* src = (blockIdx.y == 0) ? wq : (blockIdx.y == 1) ? wk : wv;
    __half* dst = (blockIdx.y == 0) ? g_wq : (blockIdx.y == 1) ? g_wk : g_wv;
    const int i = blockIdx.x * 256 + threadIdx.x;
    const float4 v0 = ((const float4*)src)[2 * i];
    const float4 v1 = ((const float4*)src)[2 * i + 1];
    __half2 h0 = __floats2half2_rn(v0.x, v0.y);
    __half2 h1 = __floats2half2_rn(v0.z, v0.w);
    __half2 h2 = __floats2half2_rn(v1.x, v1.y);
    __half2 h3 = __floats2half2_rn(v1.z, v1.w);
    uint4 o;
    o.x = *(uint32_t*)&h0; o.y = *(uint32_t*)&h1;
    o.z = *(uint32_t*)&h2; o.w = *(uint32_t*)&h3;
    *(uint4*)&dst[8 * (size_t)i] = o;
}

// ---------------- merged projection GEMM (fp16 mma) --------------------------
// blockIdx.z = mode: 0 Q (elu+1,*mask_q), 1 K (elu+1,*mask_kv), 2 V (*mask_kv)
// 128x128 tile, BK=64 halves, 3-stage cp.async, 1 barrier/iter,
// ldmatrix x4 for A and paired-B, 8 warps (2M x 4N).
#define HBM_ 128
#define HBN_ 128
#define HBK_ 64
#define HSTG_BYTES (128 * 128)
#define HNSTAGE 3
#define HNKT (C_ / HBK_)          // 16
#define PROJ_SMEM (HNSTAGE * 2 * HSTG_BYTES)   // 98304 B

__global__ __launch_bounds__(256, 2) void proj_all(
        const float* __restrict__ bq, const float* __restrict__ bk,
        const float* __restrict__ bv,
        const float* __restrict__ mask_q, const float* __restrict__ mask_kv) {
    const int mode = blockIdx.z;
    __half* out = (mode == 0) ? g_qh : (mode == 1) ? g_kh : g_vh;
    const __half* __restrict__ Xh = (mode == 0) ? g_xq : (mode == 1) ? g_xk : g_xv;
    const __half* __restrict__ Wh = (mode == 0) ? g_wq : (mode == 1) ? g_wk : g_wv;
    const float* bias = (mode == 0) ? bq : (mode == 1) ? bk : bv;
    const float* mask = (mode == 0) ? mask_q : mask_kv;
    const bool do_elu = (mode < 2);

    extern __shared__ char smem[];
    const uint32_t sb = (uint32_t)__cvta_generic_to_shared(smem);
    const int tid  = threadIdx.x;
    const int warp = tid >> 5;
    const int lane = tid & 31;
    const int wm   = warp & 1;    // 2 warps along M (64 rows)
    const int wn   = warp >> 1;   // 4 warps along N (32 cols)
    const int m0   = blockIdx.y * HBM_;
    const int n0   = blockIdx.x * HBN_;

    const int crow = tid >> 1;
    const int cch0 = (tid & 1) * 4;
    const __half* gA = Xh + (size_t)(m0 + crow) * C_ + cch0 * 8;
    const __half* gB = Wh + (size_t)(n0 + crow) * C_ + cch0 * 8;

    auto fill = [&](int stg, int s) {
        const int k0 = s * HBK_;
        const uint32_t sA = sb + (uint32_t)(stg * 2) * HSTG_BYTES;
        const uint32_t sB = sA + HSTG_BYTES;
#pragma unroll
        for (int c = 0; c < 4; c++) {
            const uint32_t off = SW128((uint32_t)(crow * 128 + (cch0 + c) * 16));
            cp16(sA + off, gA + k0 + c * 8);
            cp16(sB + off, gB + k0 + c * 8);
        }
        asm volatile("cp.async.commit_group;\n" ::: "memory");
    };

    float acc[4][4][4];
#pragma unroll
    for (int i = 0; i < 4; i++)
#pragma unroll
        for (int j = 0; j < 4; j++)
#pragma unroll
            for (int r = 0; r < 4; r++) acc[i][j][r] = 0.f;

    // A ldmatrix x4 offsets: 16 m-rows x 32B of k
    const int lm  = lane & 15;
    const int lka = (lane >> 4) * 16;
    uint32_t offA[4];
#pragma unroll
    for (int mt = 0; mt < 4; mt++)
        offA[mt] = (uint32_t)((wm * 64 + mt * 16 + lm) * 128 + lka);

    // B paired ldmatrix x4: matrices [nt0/k0, nt0/k8, nt1/k0, nt1/k8]
    const int bgrp = lane >> 3;                 // matrix index 0..3
    const int bnt  = (bgrp >> 1) * 8;           // +0 or +8 n-rows
    const int bko  = (bgrp & 1) * 16;           // +0 or +16 bytes of k
    uint32_t offB2[2];
#pragma unroll
    for (int pr = 0; pr < 2; pr++)
        offB2[pr] = (uint32_t)((wn * 32 + pr * 16 + bnt + (lane & 7)) * 128 + bko);

    fill(0, 0);
    fill(1, 1);

    for (int kt = 0; kt < HNKT; kt++) {
        if (kt + 1 < HNKT)
            asm volatile("cp.async.wait_group 1;\n" ::: "memory");
        else
            asm volatile("cp.async.wait_group 0;\n" ::: "memory");
        __syncthreads();
        if (kt + 2 < HNKT) fill((kt + 2) % HNSTAGE, kt + 2);

        const int stg = kt % HNSTAGE;
        const uint32_t sA = sb + (uint32_t)(stg * 2) * HSTG_BYTES;
        const uint32_t sB = sA + HSTG_BYTES;

#pragma unroll
        for (int ks = 0; ks < 4; ks++) {
            const uint32_t kb = (uint32_t)(ks * 32);
            uint32_t a[4][4], b[4][2];
#pragma unroll
            for (int mt = 0; mt < 4; mt++)
                ldsm_x4(a[mt][0], a[mt][1], a[mt][2], a[mt][3],
                        sA + SW128(offA[mt] + kb));
#pragma unroll
            for (int pr = 0; pr < 2; pr++)
                ldsm_x4(b[pr * 2][0], b[pr * 2][1], b[pr * 2 + 1][0], b[pr * 2 + 1][1],
                        sB + SW128(offB2[pr] + kb));
#pragma unroll
            for (int mt = 0; mt < 4; mt++)
#pragma unroll
                for (int nt = 0; nt < 4; nt++)
                    mma_f16(acc[mt][nt], a[mt][0], a[mt][1], a[mt][2], a[mt][3],
                            b[nt][0], b[nt][1]);
        }
    }

    // epilogue: +bias, feature map (Q/K), per-token mask; half2 stores
#pragma unroll
    for (int mt = 0; mt < 4; mt++) {
#pragma unroll
        for (int nt = 0; nt < 4; nt++) {
#pragma unroll
            for (int half_i = 0; half_i < 2; half_i++) {
                const int row = m0 + wm * 64 + mt * 16 + (lane >> 2) + half_i * 8;
                const int col = n0 + wn * 32 + nt * 8 + (lane & 3) * 2;
                float v0 = acc[mt][nt][half_i * 2 + 0] + bias[col + 0];
                float v1 = acc[mt][nt][half_i * 2 + 1] + bias[col + 1];
                if (do_elu) {
                    v0 = (v0 > 0.f) ? v0 + 1.f : expf(v0);
                    v1 = (v1 > 0.f) ? v1 + 1.f : expf(v1);
                }
                const float mk = mask[row];
                v0 *= mk; v1 *= mk;
                *(__half2*)&out[(size_t)row * C_ + col] = __floats2half2_rn(v0, v1);
            }
        }
    }
}

// ---------------- phase 2: partial kv = K^T V via fp16 mma ------------------
#define KVSTR 72   // halves per row: 144B = 9*16B (aligned, conflict-free)

__global__ __launch_bounds__(128) void kv_kernel() {
    const int bh = blockIdx.x;
    const int ch = blockIdx.y;
    const int b = bh >> 4, h = bh & 15;

    __shared__ __half Ks[64][KVSTR];
    __shared__ __half Vs[64][KVSTR];

    const int tid  = threadIdx.x;
    const int warp = tid >> 5;
    const int lane = tid & 31;
    const int gid  = lane >> 2;
    const int tig  = lane & 3;

    const size_t base = ((size_t)b * L_ + ch * 512) * C_ + h * D_;
    const __half* kb = g_kh + base;
    const __half* vb = g_vh + base;

    float acc[4][2][4];
#pragma unroll
    for (int i = 0; i < 4; i++)
#pragma unroll
        for (int j = 0; j < 2; j++)
#pragma unroll
            for (int r = 0; r < 4; r++) acc[i][j][r] = 0.f;
    float sk = 0.f;

    const int ti   = lane & 7;
    const int tsel = lane >> 3;
    const int arow_off = ((tsel & 2) ? 8 : 0) + ti;
    const int acol_off = ((tsel & 1) ? 8 : 0);
    const int brow_off = ((tsel & 1) ? 8 : 0) + ti;

    for (int t0 = 0; t0 < 512; t0 += 64) {
#pragma unroll
        for (int i = 0; i < 4; i++) {
            const int c = tid + i * 128;
            const int r = c >> 3, co = (c & 7) * 8;
            *(uint4*)&Ks[r][co] = *(const uint4*)&kb[(size_t)(t0 + r) * C_ + co];
            *(uint4*)&Vs[r][co] = *(const uint4*)&vb[(size_t)(t0 + r) * C_ + co];
        }
        __syncthreads();

        if (tid < 64) {
#pragma unroll 8
            for (int l = 0; l < 64; l++) sk += __half2float(Ks[l][tid]);
        }

#pragma unroll
        for (int kk = 0; kk < 64; kk += 16) {
            uint32_t a[4][4], bfr[2][2];
#pragma unroll
            for (int mt = 0; mt < 4; mt++) {
                const uint32_t addr = (uint32_t)__cvta_generic_to_shared(
                    &Ks[kk + arow_off][mt * 16 + acol_off]);
                ldsm_x4_t(a[mt][0], a[mt][1], a[mt][2], a[mt][3], addr);
            }
#pragma unroll
            for (int nt = 0; nt < 2; nt++) {
                const uint32_t addr = (uint32_t)__cvta_generic_to_shared(
                    &Vs[kk + brow_off][warp * 16 + nt * 8]);
                ldsm_x2_t(bfr[nt][0], bfr[nt][1], addr);
            }
#pragma unroll
            for (int mt = 0; mt < 4; mt++)
#pragma unroll
                for (int nt = 0; nt < 2; nt++)
                    mma_f16(acc[mt][nt], a[mt][0], a[mt][1], a[mt][2], a[mt][3],
                            bfr[nt][0], bfr[nt][1]);
        }
        __syncthreads();
    }

    float* outp = g_kvp + (size_t)(bh * 8 + ch) * D_ * D_;
#pragma unroll
    for (int mt = 0; mt < 4; mt++) {
#pragma unroll
        for (int nt = 0; nt < 2; nt++) {
#pragma unroll
            for (int half_i = 0; half_i < 2; half_i++) {
                const int d = mt * 16 + gid + half_i * 8;
                const int e = warp * 16 + nt * 8 + tig * 2;
                float2 o = make_float2(acc[mt][nt][half_i * 2 + 0],
                                       acc[mt][nt][half_i * 2 + 1]);
                *(float2*)&outp[d * D_ + e] = o;
            }
        }
    }
    if (tid < 64) g_skp[(bh * 8 + ch) * D_ + tid] = sk;
}

// ---------------- phase 2b: reduce chunk partials ---------------------------
__global__ __launch_bounds__(256) void reduce_kernel() {
    const int bh = blockIdx.x;
    const int tid = threadIdx.x;
    for (int idx = tid; idx < D_ * D_; idx += 256) {
        float s = 0.f;
#pragma unroll
        for (int c = 0; c < 8; c++) s += g_kvp[(size_t)(bh * 8 + c) * D_ * D_ + idx];
        g_kv[(size_t)bh * D_ * D_ + idx] = s;
    }
    if (tid < 64) {
        float s = 0.f;
#pragma unroll
        for (int c = 0; c < 8; c++) s += g_skp[(bh * 8 + c) * D_ + tid];
        g_sk[bh * D_ + tid] = s;
    }
}

// ---------------- phase 3: out = (q @ kv) * denom ---------------------------
__global__ __launch_bounds__(256) void out_kernel(float* __restrict__ out) {
    const int bh = blockIdx.x;
    const int lc = blockIdx.y;
    const int b = bh >> 4, h = bh & 15;

    __shared__ float qs[64][68];
    __shared__ float kvs[64][68];
    __shared__ float sks[64];
    __shared__ float den[64];

    const int tid = threadIdx.x;
    const int tx = tid & 15, ty = tid >> 4;
    const int lr = tid >> 4, lv = tid & 15;

    const __half* qb = g_qh + ((size_t)b * L_ + lc * 64) * C_ + h * D_;
#pragma unroll
    for (int i = 0; i < 4; i++) {
        const int r = lr + i * 16;
        const __half2* qp = (const __half2*)&qb[(size_t)r * C_ + lv * 4];
        float2 q0 = __half22float2(qp[0]), q1 = __half22float2(qp[1]);
        qs[r][lv * 4 + 0] = q0.x; qs[r][lv * 4 + 1] = q0.y;
        qs[r][lv * 4 + 2] = q1.x; qs[r][lv * 4 + 3] = q1.y;
        *(float4*)&kvs[r][lv * 4] = *(const float4*)&g_kv[(size_t)bh * D_ * D_ + r * D_ + lv * 4];
    }
    if (tid < 64) sks[tid] = g_sk[bh * D_ + tid];
    __syncthreads();

    if (tid < 64) {
        float s = 0.f;
#pragma unroll 16
        for (int d = 0; d < 64; d++) s += qs[tid][d] * sks[d];
        den[tid] = 1.f / (1e-6f + s);
    }
    __syncthreads();

    float acc[4][4];
#pragma unroll
    for (int i = 0; i < 4; i++)
#pragma unroll
        for (int j = 0; j < 4; j++) acc[i][j] = 0.f;

#pragma unroll 4
    for (int d = 0; d < 64; d++) {
        const float4 kv4 = *(const float4*)&kvs[d][tx * 4];
#pragma unroll
        for (int i = 0; i < 4; i++) {
            const float qv = qs[ty * 4 + i][d];
            acc[i][0] += qv * kv4.x; acc[i][1] += qv * kv4.y;
            acc[i][2] += qv * kv4.z; acc[i][3] += qv * kv4.w;
        }
    }

#pragma unroll
    for (int i = 0; i < 4; i++) {
        const int l = lc * 64 + ty * 4 + i;
        const float dn = den[ty * 4 + i];
        float4 o = make_float4(acc[i][0] * dn, acc[i][1] * dn,
                               acc[i][2] * dn, acc[i][3] * dn);
        *(float4*)&out[((size_t)b * L_ + l) * C_ + h * D_ + tx * 4] = o;
    }
}

// ---------------- launch ----------------------------------------------------
extern "C" void kernel_launch(void* const* d_in, const int* in_sizes, int n_in,
                              void* d_out, int out_size) {
    const float* query   = (const float*)d_in[0];
    const float* key     = (const float*)d_in[1];
    const float* value   = (const float*)d_in[2];
    const float* mask_q  = (const float*)d_in[3];
    const float* mask_kv = (const float*)d_in[4];
    const float* Wq = (const float*)d_in[5];
    const float* bq = (const float*)d_in[6];
    const float* Wk = (const float*)d_in[7];
    const float* bk = (const float*)d_in[8];
    const float* Wv = (const float*)d_in[9];
    const float* bv = (const float*)d_in[10];
    float* out = (float*)d_out;

    static bool attr_done = false;
    if (!attr_done) {
        cudaFuncSetAttribute(proj_all,
            cudaFuncAttributeMaxDynamicSharedMemorySize, PROJ_SMEM);
        attr_done = true;
    }

    dim3 pg(C_ / HBN_, MTOT / HBM_, 3);        // (8, 128, 3)
    dim3 cx(MTOT * C_ / 8 / 256, 3);           // (8192, 3)
    dim3 cw(C_ * C_ / 8 / 256, 3);             // (512, 3)

    cvt_x3<<<cx, 256>>>(query, key, value);
    cvt_w3<<<cw, 256>>>(Wq, Wk, Wv);

    proj_all<<<pg, 256, PROJ_SMEM>>>(bq, bk, bv, mask_q, mask_kv);

    kv_kernel<<<dim3(64, 8), 128>>>();
    reduce_kernel<<<64, 256>>>();
    out_kernel<<<dim3(64, 64), 256>>>(out);
}

// round 12
// speedup vs baseline: 2.4777x; 1.0187x over previous
#include <cuda_runtime.h>
#include <cuda_fp16.h>
#include <cstdint>

// Problem constants
#define B_    4
#define L_    4096
#define C_    1024
#define H_    16
#define D_    64
#define MTOT  (B_*L_)      // 16384

// ---------------- scratch (device globals; no allocations allowed) ----------
__device__ __half g_qh[MTOT * C_];         // 32 MB (fp16 intermediates)
__device__ __half g_kh[MTOT * C_];         // 32 MB
__device__ __half g_vh[MTOT * C_];         // 32 MB
__device__ __half g_xq[MTOT * C_];         // 32 MB fp16 inputs
__device__ __half g_xk[MTOT * C_];         // 32 MB
__device__ __half g_xv[MTOT * C_];         // 32 MB
__device__ __half g_wq[C_ * C_];           // 2 MB fp16 weights
__device__ __half g_wk[C_ * C_];
__device__ __half g_wv[C_ * C_];
__device__ float  g_kvp[64 * 8 * D_ * D_]; // partial kv per (b,h,chunk)
__device__ float  g_skp[64 * 8 * D_];      // partial summed_k
__device__ float  g_kv[64 * D_ * D_];      // reduced kv
__device__ float  g_sk[64 * D_];           // reduced summed_k

// ---------------- helpers ----------------------------------------------------
__device__ __forceinline__ void mma_f16(float c[4],
        uint32_t a0, uint32_t a1, uint32_t a2, uint32_t a3,
        uint32_t b0, uint32_t b1) {
    asm volatile(
        "mma.sync.aligned.m16n8k16.row.col.f32.f16.f16.f32 "
        "{%0,%1,%2,%3}, {%4,%5,%6,%7}, {%8,%9}, {%0,%1,%2,%3};\n"
        : "+f"(c[0]), "+f"(c[1]), "+f"(c[2]), "+f"(c[3])
        : "r"(a0), "r"(a1), "r"(a2), "r"(a3), "r"(b0), "r"(b1));
}

__device__ __forceinline__ void cp16(uint32_t saddr, const void* gaddr) {
    asm volatile("cp.async.cg.shared.global [%0], [%1], 16;\n"
                 :: "r"(saddr), "l"(gaddr));
}

__device__ __forceinline__ void ldsm_x4(uint32_t& r0, uint32_t& r1,
                                        uint32_t& r2, uint32_t& r3,
                                        uint32_t addr) {
    asm volatile("ldmatrix.sync.aligned.m8n8.x4.shared.b16 {%0,%1,%2,%3}, [%4];"
                 : "=r"(r0), "=r"(r1), "=r"(r2), "=r"(r3) : "r"(addr));
}

__device__ __forceinline__ void ldsm_x4_t(uint32_t& r0, uint32_t& r1,
                                          uint32_t& r2, uint32_t& r3,
                                          uint32_t addr) {
    asm volatile("ldmatrix.sync.aligned.m8n8.x4.trans.shared.b16 {%0,%1,%2,%3}, [%4];"
                 : "=r"(r0), "=r"(r1), "=r"(r2), "=r"(r3) : "r"(addr));
}

__device__ __forceinline__ void ldsm_x2_t(uint32_t& r0, uint32_t& r1,
                                          uint32_t addr) {
    asm volatile("ldmatrix.sync.aligned.m8n8.x2.trans.shared.b16 {%0,%1}, [%2];"
                 : "=r"(r0), "=r"(r1) : "r"(addr));
}

#define SW128(off) ((off) ^ ((((uint32_t)(off)) >> 3) & 0x70))

// ---------------- fp32 -> fp16 conversions (consolidated) --------------------
__global__ __launch_bounds__(256) void cvt_x3(
        const float* __restrict__ q, const float* __restrict__ k,
        const float* __restrict__ v) {
    const float* src = (blockIdx.y == 0) ? q : (blockIdx.y == 1) ? k : v;
    __half* dst = (blockIdx.y == 0) ? g_xq : (blockIdx.y == 1) ? g_xk : g_xv;
    const int i = blockIdx.x * 256 + threadIdx.x;
    const float4 v0 = ((const float4*)src)[2 * i];
    const float4 v1 = ((const float4*)src)[2 * i + 1];
    __half2 h0 = __floats2half2_rn(v0.x, v0.y);
    __half2 h1 = __floats2half2_rn(v0.z, v0.w);
    __half2 h2 = __floats2half2_rn(v1.x, v1.y);
    __half2 h3 = __floats2half2_rn(v1.z, v1.w);
    uint4 o;
    o.x = *(uint32_t*)&h0; o.y = *(uint32_t*)&h1;
    o.z = *(uint32_t*)&h2; o.w = *(uint32_t*)&h3;
    *(uint4*)&dst[8 * (size_t)i] = o;
}

__global__ __launch_bounds__(256) void cvt_w3(
        const float* __restrict__ wq, const float* __restrict__ wk,
        const float* __restrict__ wv) {
    const float* src = (blockIdx.y == 0) ? wq : (blockIdx.y == 1) ? wk : wv;
    __half* dst = (blockIdx.y == 0) ? g_wq : (blockIdx.y == 1) ? g_wk : g_wv;
    const int i = blockIdx.x * 256 + threadIdx.x;
    const float4 v0 = ((const float4*)src)[2 * i];
    const float4 v1 = ((const float4*)src)[2 * i + 1];
    __half2 h0 = __floats2half2_rn(v0.x, v0.y);
    __half2 h1 = __floats2half2_rn(v0.z, v0.w);
    __half2 h2 = __floats2half2_rn(v1.x, v1.y);
    __half2 h3 = __floats2half2_rn(v1.z, v1.w);
    uint4 o;
    o.x = *(uint32_t*)&h0; o.y = *(uint32_t*)&h1;
    o.z = *(uint32_t*)&h2; o.w = *(uint32_t*)&h3;
    *(uint4*)&dst[8 * (size_t)i] = o;
}

// ---------------- merged projection GEMM (fp16 mma) --------------------------
// blockIdx.z = mode: 0 Q (elu+1,*mask_q), 1 K (elu+1,*mask_kv), 2 V (*mask_kv)
#define HBM_ 128
#define HBN_ 128
#define HBK_ 64
#define HSTG_BYTES (128 * 128)
#define HNSTAGE 3
#define HNKT (C_ / HBK_)          // 16
#define PROJ_SMEM (HNSTAGE * 2 * HSTG_BYTES)   // 98304 B

__global__ __launch_bounds__(256, 2) void proj_all(
        const float* __restrict__ bq, const float* __restrict__ bk,
        const float* __restrict__ bv,
        const float* __restrict__ mask_q, const float* __restrict__ mask_kv) {
    const int mode = blockIdx.z;
    __half* out = (mode == 0) ? g_qh : (mode == 1) ? g_kh : g_vh;
    const __half* __restrict__ Xh = (mode == 0) ? g_xq : (mode == 1) ? g_xk : g_xv;
    const __half* __restrict__ Wh = (mode == 0) ? g_wq : (mode == 1) ? g_wk : g_wv;
    const float* bias = (mode == 0) ? bq : (mode == 1) ? bk : bv;
    const float* mask = (mode == 0) ? mask_q : mask_kv;
    const bool do_elu = (mode < 2);

    extern __shared__ char smem[];
    const uint32_t sb = (uint32_t)__cvta_generic_to_shared(smem);
    const int tid  = threadIdx.x;
    const int warp = tid >> 5;
    const int lane = tid & 31;
    const int wm   = warp & 1;    // 2 warps along M (64 rows)
    const int wn   = warp >> 1;   // 4 warps along N (32 cols)
    const int m0   = blockIdx.y * HBM_;
    const int n0   = blockIdx.x * HBN_;

    const int crow = tid >> 1;
    const int cch0 = (tid & 1) * 4;
    const __half* gA = Xh + (size_t)(m0 + crow) * C_ + cch0 * 8;
    const __half* gB = Wh + (size_t)(n0 + crow) * C_ + cch0 * 8;

    auto fill = [&](int stg, int s) {
        const int k0 = s * HBK_;
        const uint32_t sA = sb + (uint32_t)(stg * 2) * HSTG_BYTES;
        const uint32_t sB = sA + HSTG_BYTES;
#pragma unroll
        for (int c = 0; c < 4; c++) {
            const uint32_t off = SW128((uint32_t)(crow * 128 + (cch0 + c) * 16));
            cp16(sA + off, gA + k0 + c * 8);
            cp16(sB + off, gB + k0 + c * 8);
        }
        asm volatile("cp.async.commit_group;\n" ::: "memory");
    };

    float acc[4][4][4];
#pragma unroll
    for (int i = 0; i < 4; i++)
#pragma unroll
        for (int j = 0; j < 4; j++)
#pragma unroll
            for (int r = 0; r < 4; r++) acc[i][j][r] = 0.f;

    // A ldmatrix x4 offsets: 16 m-rows x 32B of k
    const int lm  = lane & 15;
    const int lka = (lane >> 4) * 16;
    uint32_t offA[4];
#pragma unroll
    for (int mt = 0; mt < 4; mt++)
        offA[mt] = (uint32_t)((wm * 64 + mt * 16 + lm) * 128 + lka);

    // B paired ldmatrix x4: matrices [nt0/k0, nt0/k8, nt1/k0, nt1/k8]
    const int bgrp = lane >> 3;                 // matrix index 0..3
    const int bnt  = (bgrp >> 1) * 8;           // +0 or +8 n-rows
    const int bko  = (bgrp & 1) * 16;           // +0 or +16 bytes of k
    uint32_t offB2[2];
#pragma unroll
    for (int pr = 0; pr < 2; pr++)
        offB2[pr] = (uint32_t)((wn * 32 + pr * 16 + bnt + (lane & 7)) * 128 + bko);

    fill(0, 0);
    fill(1, 1);

    for (int kt = 0; kt < HNKT; kt++) {
        if (kt + 1 < HNKT)
            asm volatile("cp.async.wait_group 1;\n" ::: "memory");
        else
            asm volatile("cp.async.wait_group 0;\n" ::: "memory");
        __syncthreads();
        if (kt + 2 < HNKT) fill((kt + 2) % HNSTAGE, kt + 2);

        const int stg = kt % HNSTAGE;
        const uint32_t sA = sb + (uint32_t)(stg * 2) * HSTG_BYTES;
        const uint32_t sB = sA + HSTG_BYTES;

#pragma unroll
        for (int ks = 0; ks < 4; ks++) {
            const uint32_t kb = (uint32_t)(ks * 32);
            uint32_t a[4][4], b[4][2];
            // B first: consumed earliest by the mma sequence
#pragma unroll
            for (int pr = 0; pr < 2; pr++)
                ldsm_x4(b[pr * 2][0], b[pr * 2][1], b[pr * 2 + 1][0], b[pr * 2 + 1][1],
                        sB + SW128(offB2[pr] + kb));
#pragma unroll
            for (int mt = 0; mt < 4; mt++)
                ldsm_x4(a[mt][0], a[mt][1], a[mt][2], a[mt][3],
                        sA + SW128(offA[mt] + kb));
#pragma unroll
            for (int mt = 0; mt < 4; mt++)
#pragma unroll
                for (int nt = 0; nt < 4; nt++)
                    mma_f16(acc[mt][nt], a[mt][0], a[mt][1], a[mt][2], a[mt][3],
                            b[nt][0], b[nt][1]);
        }
    }

    // epilogue: +bias, feature map (Q/K), per-token mask; half2 stores
#pragma unroll
    for (int mt = 0; mt < 4; mt++) {
#pragma unroll
        for (int nt = 0; nt < 4; nt++) {
#pragma unroll
            for (int half_i = 0; half_i < 2; half_i++) {
                const int row = m0 + wm * 64 + mt * 16 + (lane >> 2) + half_i * 8;
                const int col = n0 + wn * 32 + nt * 8 + (lane & 3) * 2;
                float v0 = acc[mt][nt][half_i * 2 + 0] + bias[col + 0];
                float v1 = acc[mt][nt][half_i * 2 + 1] + bias[col + 1];
                if (do_elu) {
                    v0 = (v0 > 0.f) ? v0 + 1.f : expf(v0);
                    v1 = (v1 > 0.f) ? v1 + 1.f : expf(v1);
                }
                const float mk = mask[row];
                v0 *= mk; v1 *= mk;
                *(__half2*)&out[(size_t)row * C_ + col] = __floats2half2_rn(v0, v1);
            }
        }
    }
}

// ---------------- phase 2: partial kv = K^T V via fp16 mma ------------------
// 256 threads, 8 warps x 8 output cols, cp.async double-buffered 64-token tiles
#define KVSTR 72   // halves per row: 144B = 9*16B (aligned, conflict-free)
#define KVROWB (KVSTR * 2)            // 144 bytes per row
#define KVARR  (64 * KVROWB)          // 9216 B per array per stage

__global__ __launch_bounds__(256) void kv_kernel() {
    const int bh = blockIdx.x;   // b*16+h
    const int ch = blockIdx.y;   // L chunk of 512
    const int b = bh >> 4, h = bh & 15;

    // [stage][arr(K=0,V=1)][row][col]
    __shared__ __align__(16) __half skv[2][2][64][KVSTR];
    const uint32_t sbase = (uint32_t)__cvta_generic_to_shared(skv);

    const int tid  = threadIdx.x;
    const int warp = tid >> 5;
    const int lane = tid & 31;
    const int gid  = lane >> 2;
    const int tig  = lane & 3;

    const size_t base = ((size_t)b * L_ + ch * 512) * C_ + h * D_;
    const __half* kb = g_kh + base;
    const __half* vb = g_vh + base;

    float acc[4][4];
#pragma unroll
    for (int i = 0; i < 4; i++)
#pragma unroll
        for (int j = 0; j < 4; j++) acc[i][j] = 0.f;
    float sk = 0.f;

    // loader mapping: chunk c (0..1023): arr = c>>9, cc = c&511, r = cc>>3,
    // col = (cc&7)*8 halves (16B). 4 chunks per thread.
    auto fill = [&](int stg, int t0) {
#pragma unroll
        for (int i = 0; i < 4; i++) {
            const int c  = tid + i * 256;
            const int ar = c >> 9;
            const int cc = c & 511;
            const int r  = cc >> 3;
            const int co = (cc & 7) * 8;                 // halves
            const __half* src = (ar ? vb : kb) + (size_t)(t0 + r) * C_ + co;
            const uint32_t dst = sbase
                + (uint32_t)((stg * 2 + ar) * KVARR + r * KVROWB + co * 2);
            cp16(dst, src);
        }
        asm volatile("cp.async.commit_group;\n" ::: "memory");
    };

    // ldmatrix.trans per-thread row/col offsets
    const int ti   = lane & 7;
    const int tsel = lane >> 3;
    const int arow_off = ((tsel & 2) ? 8 : 0) + ti;
    const int acol_off = ((tsel & 1) ? 8 : 0);
    const int brow_off = ((tsel & 1) ? 8 : 0) + ti;
    const int c0 = warp * 8;                  // this warp's output cols

    fill(0, 0);

    for (int t = 0; t < 8; t++) {
        asm volatile("cp.async.wait_group 0;\n" ::: "memory");
        __syncthreads();
        if (t + 1 < 8) fill((t + 1) & 1, (t + 1) * 64);

        const int st = t & 1;

        if (tid < 64) {
#pragma unroll 8
            for (int l = 0; l < 64; l++) sk += __half2float(skv[st][0][l][tid]);
        }

#pragma unroll
        for (int kk = 0; kk < 64; kk += 16) {
            uint32_t a[4][4], b0, b1;
            {
                const uint32_t addr = (uint32_t)__cvta_generic_to_shared(
                    &skv[st][1][kk + brow_off][c0]);
                ldsm_x2_t(b0, b1, addr);
            }
#pragma unroll
            for (int mt = 0; mt < 4; mt++) {
                const uint32_t addr = (uint32_t)__cvta_generic_to_shared(
                    &skv[st][0][kk + arow_off][mt * 16 + acol_off]);
                ldsm_x4_t(a[mt][0], a[mt][1], a[mt][2], a[mt][3], addr);
            }
#pragma unroll
            for (int mt = 0; mt < 4; mt++)
                mma_f16(acc[mt], a[mt][0], a[mt][1], a[mt][2], a[mt][3], b0, b1);
        }
    }

    float* outp = g_kvp + (size_t)(bh * 8 + ch) * D_ * D_;
#pragma unroll
    for (int mt = 0; mt < 4; mt++) {
#pragma unroll
        for (int half_i = 0; half_i < 2; half_i++) {
            const int d = mt * 16 + gid + half_i * 8;
            const int e = c0 + tig * 2;
            float2 o = make_float2(acc[mt][half_i * 2 + 0],
                                   acc[mt][half_i * 2 + 1]);
            *(float2*)&outp[d * D_ + e] = o;
        }
    }
    if (tid < 64) g_skp[(bh * 8 + ch) * D_ + tid] = sk;
}

// ---------------- phase 2b: reduce chunk partials ---------------------------
__global__ __launch_bounds__(256) void reduce_kernel() {
    const int bh = blockIdx.x;
    const int tid = threadIdx.x;
    for (int idx = tid; idx < D_ * D_; idx += 256) {
        float s = 0.f;
#pragma unroll
        for (int c = 0; c < 8; c++) s += g_kvp[(size_t)(bh * 8 + c) * D_ * D_ + idx];
        g_kv[(size_t)bh * D_ * D_ + idx] = s;
    }
    if (tid < 64) {
        float s = 0.f;
#pragma unroll
        for (int c = 0; c < 8; c++) s += g_skp[(bh * 8 + c) * D_ + tid];
        g_sk[bh * D_ + tid] = s;
    }
}

// ---------------- phase 3: out = (q @ kv) * denom ---------------------------
__global__ __launch_bounds__(256) void out_kernel(float* __restrict__ out) {
    const int bh = blockIdx.x;
    const int lc = blockIdx.y;
    const int b = bh >> 4, h = bh & 15;

    __shared__ float qs[64][68];
    __shared__ float kvs[64][68];
    __shared__ float sks[64];
    __shared__ float den[64];

    const int tid = threadIdx.x;
    const int tx = tid & 15, ty = tid >> 4;
    const int lr = tid >> 4, lv = tid & 15;

    const __half* qb = g_qh + ((size_t)b * L_ + lc * 64) * C_ + h * D_;
#pragma unroll
    for (int i = 0; i < 4; i++) {
        const int r = lr + i * 16;
        const __half2* qp = (const __half2*)&qb[(size_t)r * C_ + lv * 4];
        float2 q0 = __half22float2(qp[0]), q1 = __half22float2(qp[1]);
        qs[r][lv * 4 + 0] = q0.x; qs[r][lv * 4 + 1] = q0.y;
        qs[r][lv * 4 + 2] = q1.x; qs[r][lv * 4 + 3] = q1.y;
        *(float4*)&kvs[r][lv * 4] = *(const float4*)&g_kv[(size_t)bh * D_ * D_ + r * D_ + lv * 4];
    }
    if (tid < 64) sks[tid] = g_sk[bh * D_ + tid];
    __syncthreads();

    if (tid < 64) {
        float s = 0.f;
#pragma unroll 16
        for (int d = 0; d < 64; d++) s += qs[tid][d] * sks[d];
        den[tid] = 1.f / (1e-6f + s);
    }
    __syncthreads();

    float acc[4][4];
#pragma unroll
    for (int i = 0; i < 4; i++)
#pragma unroll
        for (int j = 0; j < 4; j++) acc[i][j] = 0.f;

#pragma unroll 4
    for (int d = 0; d < 64; d++) {
        const float4 kv4 = *(const float4*)&kvs[d][tx * 4];
#pragma unroll
        for (int i = 0; i < 4; i++) {
            const float qv = qs[ty * 4 + i][d];
            acc[i][0] += qv * kv4.x; acc[i][1] += qv * kv4.y;
            acc[i][2] += qv * kv4.z; acc[i][3] += qv * kv4.w;
        }
    }

#pragma unroll
    for (int i = 0; i < 4; i++) {
        const int l = lc * 64 + ty * 4 + i;
        const float dn = den[ty * 4 + i];
        float4 o = make_float4(acc[i][0] * dn, acc[i][1] * dn,
                               acc[i][2] * dn, acc[i][3] * dn);
        *(float4*)&out[((size_t)b * L_ + l) * C_ + h * D_ + tx * 4] = o;
    }
}

// ---------------- launch ----------------------------------------------------
extern "C" void kernel_launch(void* const* d_in, const int* in_sizes, int n_in,
                              void* d_out, int out_size) {
    const float* query   = (const float*)d_in[0];
    const float* key     = (const float*)d_in[1];
    const float* value   = (const float*)d_in[2];
    const float* mask_q  = (const float*)d_in[3];
    const float* mask_kv = (const float*)d_in[4];
    const float* Wq = (const float*)d_in[5];
    const float* bq = (const float*)d_in[6];
    const float* Wk = (const float*)d_in[7];
    const float* bk = (const float*)d_in[8];
    const float* Wv = (const float*)d_in[9];
    const float* bv = (const float*)d_in[10];
    float* out = (float*)d_out;

    static bool attr_done = false;
    if (!attr_done) {
        cudaFuncSetAttribute(proj_all,
            cudaFuncAttributeMaxDynamicSharedMemorySize, PROJ_SMEM);
        attr_done = true;
    }

    dim3 pg(C_ / HBN_, MTOT / HBM_, 3);        // (8, 128, 3)
    dim3 cx(MTOT * C_ / 8 / 256, 3);           // (8192, 3)
    dim3 cw(C_ * C_ / 8 / 256, 3);             // (512, 3)

    cvt_x3<<<cx, 256>>>(query, key, value);
    cvt_w3<<<cw, 256>>>(Wq, Wk, Wv);

    proj_all<<<pg, 256, PROJ_SMEM>>>(bq, bk, bv, mask_q, mask_kv);

    kv_kernel<<<dim3(64, 8), 256>>>();
    reduce_kernel<<<64, 256>>>();
    out_kernel<<<dim3(64, 64), 256>>>(out);
}

// round 13
// speedup vs baseline: 2.4870x; 1.0037x over previous
#include <cuda_runtime.h>
#include <cuda_fp16.h>
#include <cstdint>

// Problem constants
#define B_    4
#define L_    4096
#define C_    1024
#define H_    16
#define D_    64
#define MTOT  (B_*L_)      // 16384

// ---------------- scratch (device globals; no allocations allowed) ----------
__device__ __half g_qh[MTOT * C_];         // 32 MB (fp16 intermediates)
__device__ __half g_kh[MTOT * C_];         // 32 MB
__device__ __half g_vh[MTOT * C_];         // 32 MB
__device__ __half g_xq[MTOT * C_];         // 32 MB fp16 inputs
__device__ __half g_xk[MTOT * C_];         // 32 MB
__device__ __half g_xv[MTOT * C_];         // 32 MB
__device__ __half g_wq[C_ * C_];           // 2 MB fp16 weights
__device__ __half g_wk[C_ * C_];
__device__ __half g_wv[C_ * C_];
__device__ float  g_kvp[64 * 8 * D_ * D_]; // partial kv per (b,h,chunk)
__device__ float  g_skp[64 * 8 * D_];      // partial summed_k
__device__ float  g_kv[64 * D_ * D_];      // reduced kv
__device__ float  g_sk[64 * D_];           // reduced summed_k

// ---------------- helpers ----------------------------------------------------
__device__ __forceinline__ void mma_f16(float c[4],
        uint32_t a0, uint32_t a1, uint32_t a2, uint32_t a3,
        uint32_t b0, uint32_t b1) {
    asm volatile(
        "mma.sync.aligned.m16n8k16.row.col.f32.f16.f16.f32 "
        "{%0,%1,%2,%3}, {%4,%5,%6,%7}, {%8,%9}, {%0,%1,%2,%3};\n"
        : "+f"(c[0]), "+f"(c[1]), "+f"(c[2]), "+f"(c[3])
        : "r"(a0), "r"(a1), "r"(a2), "r"(a3), "r"(b0), "r"(b1));
}

__device__ __forceinline__ void cp16(uint32_t saddr, const void* gaddr) {
    asm volatile("cp.async.cg.shared.global [%0], [%1], 16;\n"
                 :: "r"(saddr), "l"(gaddr));
}

__device__ __forceinline__ void ldsm_x4(uint32_t& r0, uint32_t& r1,
                                        uint32_t& r2, uint32_t& r3,
                                        uint32_t addr) {
    asm volatile("ldmatrix.sync.aligned.m8n8.x4.shared.b16 {%0,%1,%2,%3}, [%4];"
                 : "=r"(r0), "=r"(r1), "=r"(r2), "=r"(r3) : "r"(addr));
}

__device__ __forceinline__ void ldsm_x4_t(uint32_t& r0, uint32_t& r1,
                                          uint32_t& r2, uint32_t& r3,
                                          uint32_t addr) {
    asm volatile("ldmatrix.sync.aligned.m8n8.x4.trans.shared.b16 {%0,%1,%2,%3}, [%4];"
                 : "=r"(r0), "=r"(r1), "=r"(r2), "=r"(r3) : "r"(addr));
}

#define SW128(off) ((off) ^ ((((uint32_t)(off)) >> 3) & 0x70))

// ---------------- fp32 -> fp16 conversions (consolidated) --------------------
// 16 floats per thread (2x uint4 stores) for higher per-thread MLP.
__global__ __launch_bounds__(256) void cvt_x3(
        const float* __restrict__ q, const float* __restrict__ k,
        const float* __restrict__ v) {
    const float* src = (blockIdx.y == 0) ? q : (blockIdx.y == 1) ? k : v;
    __half* dst = (blockIdx.y == 0) ? g_xq : (blockIdx.y == 1) ? g_xk : g_xv;
    const int i = blockIdx.x * 256 + threadIdx.x;   // 0 .. MTOT*C_/16-1
    const float4 v0 = ((const float4*)src)[4 * i];
    const float4 v1 = ((const float4*)src)[4 * i + 1];
    const float4 v2 = ((const float4*)src)[4 * i + 2];
    const float4 v3 = ((const float4*)src)[4 * i + 3];
    __half2 h0 = __floats2half2_rn(v0.x, v0.y), h1 = __floats2half2_rn(v0.z, v0.w);
    __half2 h2 = __floats2half2_rn(v1.x, v1.y), h3 = __floats2half2_rn(v1.z, v1.w);
    __half2 h4 = __floats2half2_rn(v2.x, v2.y), h5 = __floats2half2_rn(v2.z, v2.w);
    __half2 h6 = __floats2half2_rn(v3.x, v3.y), h7 = __floats2half2_rn(v3.z, v3.w);
    uint4 o0, o1;
    o0.x = *(uint32_t*)&h0; o0.y = *(uint32_t*)&h1;
    o0.z = *(uint32_t*)&h2; o0.w = *(uint32_t*)&h3;
    o1.x = *(uint32_t*)&h4; o1.y = *(uint32_t*)&h5;
    o1.z = *(uint32_t*)&h6; o1.w = *(uint32_t*)&h7;
    *(uint4*)&dst[16 * (size_t)i]     = o0;
    *(uint4*)&dst[16 * (size_t)i + 8] = o1;
}

__global__ __launch_bounds__(256) void cvt_w3(
        const float* __restrict__ wq, const float* __restrict__ wk,
        const float* __restrict__ wv) {
    const float* src = (blockIdx.y == 0) ? wq : (blockIdx.y == 1) ? wk : wv;
    __half* dst = (blockIdx.y == 0) ? g_wq : (blockIdx.y == 1) ? g_wk : g_wv;
    const int i = blockIdx.x * 256 + threadIdx.x;
    const float4 v0 = ((const float4*)src)[2 * i];
    const float4 v1 = ((const float4*)src)[2 * i + 1];
    __half2 h0 = __floats2half2_rn(v0.x, v0.y);
    __half2 h1 = __floats2half2_rn(v0.z, v0.w);
    __half2 h2 = __floats2half2_rn(v1.x, v1.y);
    __half2 h3 = __floats2half2_rn(v1.z, v1.w);
    uint4 o;
    o.x = *(uint32_t*)&h0; o.y = *(uint32_t*)&h1;
    o.z = *(uint32_t*)&h2; o.w = *(uint32_t*)&h3;
    *(uint4*)&dst[8 * (size_t)i] = o;
}

// ---------------- merged projection GEMM (fp16 mma) --------------------------
// blockIdx.z = mode: 0 Q (elu+1,*mask_q), 1 K (elu+1,*mask_kv), 2 V (*mask_kv)
#define HBM_ 128
#define HBN_ 128
#define HBK_ 64
#define HSTG_BYTES (128 * 128)
#define HNSTAGE 3
#define HNKT (C_ / HBK_)          // 16
#define PROJ_SMEM (HNSTAGE * 2 * HSTG_BYTES)   // 98304 B

__global__ __launch_bounds__(256, 2) void proj_all(
        const float* __restrict__ bq, const float* __restrict__ bk,
        const float* __restrict__ bv,
        const float* __restrict__ mask_q, const float* __restrict__ mask_kv) {
    const int mode = blockIdx.z;
    __half* out = (mode == 0) ? g_qh : (mode == 1) ? g_kh : g_vh;
    const __half* __restrict__ Xh = (mode == 0) ? g_xq : (mode == 1) ? g_xk : g_xv;
    const __half* __restrict__ Wh = (mode == 0) ? g_wq : (mode == 1) ? g_wk : g_wv;
    const float* bias = (mode == 0) ? bq : (mode == 1) ? bk : bv;
    const float* mask = (mode == 0) ? mask_q : mask_kv;
    const bool do_elu = (mode < 2);

    extern __shared__ char smem[];
    const uint32_t sb = (uint32_t)__cvta_generic_to_shared(smem);
    const int tid  = threadIdx.x;
    const int warp = tid >> 5;
    const int lane = tid & 31;
    const int wm   = warp & 1;    // 2 warps along M (64 rows)
    const int wn   = warp >> 1;   // 4 warps along N (32 cols)
    const int m0   = blockIdx.y * HBM_;
    const int n0   = blockIdx.x * HBN_;

    const int crow = tid >> 1;
    const int cch0 = (tid & 1) * 4;
    const __half* gA = Xh + (size_t)(m0 + crow) * C_ + cch0 * 8;
    const __half* gB = Wh + (size_t)(n0 + crow) * C_ + cch0 * 8;

    auto fill = [&](int stg, int s) {
        const int k0 = s * HBK_;
        const uint32_t sA = sb + (uint32_t)(stg * 2) * HSTG_BYTES;
        const uint32_t sB = sA + HSTG_BYTES;
#pragma unroll
        for (int c = 0; c < 4; c++) {
            const uint32_t off = SW128((uint32_t)(crow * 128 + (cch0 + c) * 16));
            cp16(sA + off, gA + k0 + c * 8);
            cp16(sB + off, gB + k0 + c * 8);
        }
        asm volatile("cp.async.commit_group;\n" ::: "memory");
    };

    float acc[4][4][4];
#pragma unroll
    for (int i = 0; i < 4; i++)
#pragma unroll
        for (int j = 0; j < 4; j++)
#pragma unroll
            for (int r = 0; r < 4; r++) acc[i][j][r] = 0.f;

    // A ldmatrix x4 offsets: 16 m-rows x 32B of k
    const int lm  = lane & 15;
    const int lka = (lane >> 4) * 16;
    uint32_t offA[4];
#pragma unroll
    for (int mt = 0; mt < 4; mt++)
        offA[mt] = (uint32_t)((wm * 64 + mt * 16 + lm) * 128 + lka);

    // B paired ldmatrix x4: matrices [nt0/k0, nt0/k8, nt1/k0, nt1/k8]
    const int bgrp = lane >> 3;                 // matrix index 0..3
    const int bnt  = (bgrp >> 1) * 8;           // +0 or +8 n-rows
    const int bko  = (bgrp & 1) * 16;           // +0 or +16 bytes of k
    uint32_t offB2[2];
#pragma unroll
    for (int pr = 0; pr < 2; pr++)
        offB2[pr] = (uint32_t)((wn * 32 + pr * 16 + bnt + (lane & 7)) * 128 + bko);

    fill(0, 0);
    fill(1, 1);

    for (int kt = 0; kt < HNKT; kt++) {
        if (kt + 1 < HNKT)
            asm volatile("cp.async.wait_group 1;\n" ::: "memory");
        else
            asm volatile("cp.async.wait_group 0;\n" ::: "memory");
        __syncthreads();
        if (kt + 2 < HNKT) fill((kt + 2) % HNSTAGE, kt + 2);

        const int stg = kt % HNSTAGE;
        const uint32_t sA = sb + (uint32_t)(stg * 2) * HSTG_BYTES;
        const uint32_t sB = sA + HSTG_BYTES;

#pragma unroll
        for (int ks = 0; ks < 4; ks++) {
            const uint32_t kb = (uint32_t)(ks * 32);
            uint32_t a[4][4], b[4][2];
            // B first: consumed earliest by the mma sequence
#pragma unroll
            for (int pr = 0; pr < 2; pr++)
                ldsm_x4(b[pr * 2][0], b[pr * 2][1], b[pr * 2 + 1][0], b[pr * 2 + 1][1],
                        sB + SW128(offB2[pr] + kb));
#pragma unroll
            for (int mt = 0; mt < 4; mt++)
                ldsm_x4(a[mt][0], a[mt][1], a[mt][2], a[mt][3],
                        sA + SW128(offA[mt] + kb));
#pragma unroll
            for (int mt = 0; mt < 4; mt++)
#pragma unroll
                for (int nt = 0; nt < 4; nt++)
                    mma_f16(acc[mt][nt], a[mt][0], a[mt][1], a[mt][2], a[mt][3],
                            b[nt][0], b[nt][1]);
        }
    }

    // epilogue: +bias, feature map (Q/K), per-token mask; half2 stores
#pragma unroll
    for (int mt = 0; mt < 4; mt++) {
#pragma unroll
        for (int nt = 0; nt < 4; nt++) {
#pragma unroll
            for (int half_i = 0; half_i < 2; half_i++) {
                const int row = m0 + wm * 64 + mt * 16 + (lane >> 2) + half_i * 8;
                const int col = n0 + wn * 32 + nt * 8 + (lane & 3) * 2;
                float v0 = acc[mt][nt][half_i * 2 + 0] + bias[col + 0];
                float v1 = acc[mt][nt][half_i * 2 + 1] + bias[col + 1];
                if (do_elu) {
                    v0 = (v0 > 0.f) ? v0 + 1.f : expf(v0);
                    v1 = (v1 > 0.f) ? v1 + 1.f : expf(v1);
                }
                const float mk = mask[row];
                v0 *= mk; v1 *= mk;
                *(__half2*)&out[(size_t)row * C_ + col] = __floats2half2_rn(v0, v1);
            }
        }
    }
}

// ---------------- phase 2: partial kv = K^T V via fp16 mma ------------------
// 256 threads, 8 warps = 2 d-halves x 4 col-groups (32x16 output tiles).
// cp.async double-buffered 64-token tiles; 4 L-chunks of 1024 tokens.
#define KVSTR 72   // halves per row: 144B = 9*16B (aligned, conflict-free)
#define KVROWB (KVSTR * 2)            // 144 bytes per row
#define KVARR  (64 * KVROWB)          // 9216 B per array per stage
#define KVCH   4                      // L chunks
#define KVTILES 16                    // 64-token tiles per chunk

__global__ __launch_bounds__(256) void kv_kernel() {
    const int bh = blockIdx.x;   // b*16+h
    const int ch = blockIdx.y;   // L chunk of 1024
    const int b = bh >> 4, h = bh & 15;

    // [stage][arr(K=0,V=1)][row][col]
    __shared__ __align__(16) __half skv[2][2][64][KVSTR];
    const uint32_t sbase = (uint32_t)__cvta_generic_to_shared(skv);

    const int tid  = threadIdx.x;
    const int warp = tid >> 5;
    const int lane = tid & 31;
    const int gid  = lane >> 2;
    const int tig  = lane & 3;
    const int dh   = warp >> 2;           // d-half: rows [dh*32, dh*32+32)
    const int c0   = (warp & 3) * 16;     // col-group: cols [c0, c0+16)

    const size_t base = ((size_t)b * L_ + ch * 1024) * C_ + h * D_;
    const __half* kb = g_kh + base;
    const __half* vb = g_vh + base;

    float acc[2][2][4];
#pragma unroll
    for (int i = 0; i < 2; i++)
#pragma unroll
        for (int j = 0; j < 2; j++)
#pragma unroll
            for (int r = 0; r < 4; r++) acc[i][j][r] = 0.f;
    float sk = 0.f;

    auto fill = [&](int stg, int t0) {
#pragma unroll
        for (int i = 0; i < 4; i++) {
            const int c  = tid + i * 256;
            const int ar = c >> 9;
            const int cc = c & 511;
            const int r  = cc >> 3;
            const int co = (cc & 7) * 8;                 // halves
            const __half* src = (ar ? vb : kb) + (size_t)(t0 + r) * C_ + co;
            const uint32_t dst = sbase
                + (uint32_t)((stg * 2 + ar) * KVARR + r * KVROWB + co * 2);
            cp16(dst, src);
        }
        asm volatile("cp.async.commit_group;\n" ::: "memory");
    };

    // A (K) ldmatrix.trans x4 offsets: same mapping as proven R12 code
    const int ti   = lane & 7;
    const int tsel = lane >> 3;
    const int arow_off = ((tsel & 2) ? 8 : 0) + ti;
    const int acol_off = ((tsel & 1) ? 8 : 0);
    // B (V) paired ldmatrix.trans x4: groups [nt0/k-lo, nt0/k-hi, nt1/k-lo, nt1/k-hi]
    const int brow_off = ((tsel & 1) ? 8 : 0) + ti;   // + kk
    const int bcol_off = (tsel >> 1) * 8;             // + c0

    fill(0, 0);

    for (int t = 0; t < KVTILES; t++) {
        asm volatile("cp.async.wait_group 0;\n" ::: "memory");
        __syncthreads();
        if (t + 1 < KVTILES) fill((t + 1) & 1, (t + 1) * 64);

        const int st = t & 1;

        if (tid < 64) {
#pragma unroll 8
            for (int l = 0; l < 64; l++) sk += __half2float(skv[st][0][l][tid]);
        }

#pragma unroll
        for (int kk = 0; kk < 64; kk += 16) {
            uint32_t a[2][4], bf[2][2];
            {
                const uint32_t addr = (uint32_t)__cvta_generic_to_shared(
                    &skv[st][1][kk + brow_off][c0 + bcol_off]);
                ldsm_x4_t(bf[0][0], bf[0][1], bf[1][0], bf[1][1], addr);
            }
#pragma unroll
            for (int mt = 0; mt < 2; mt++) {
                const uint32_t addr = (uint32_t)__cvta_generic_to_shared(
                    &skv[st][0][kk + arow_off][(dh * 2 + mt) * 16 + acol_off]);
                ldsm_x4_t(a[mt][0], a[mt][1], a[mt][2], a[mt][3], addr);
            }
#pragma unroll
            for (int mt = 0; mt < 2; mt++)
#pragma unroll
                for (int nt = 0; nt < 2; nt++)
                    mma_f16(acc[mt][nt], a[mt][0], a[mt][1], a[mt][2], a[mt][3],
                            bf[nt][0], bf[nt][1]);
        }
    }

    float* outp = g_kvp + (size_t)(bh * KVCH + ch) * D_ * D_;
#pragma unroll
    for (int mt = 0; mt < 2; mt++) {
#pragma unroll
        for (int nt = 0; nt < 2; nt++) {
#pragma unroll
            for (int half_i = 0; half_i < 2; half_i++) {
                const int d = dh * 32 + mt * 16 + gid + half_i * 8;
                const int e = c0 + nt * 8 + tig * 2;
                float2 o = make_float2(acc[mt][nt][half_i * 2 + 0],
                                       acc[mt][nt][half_i * 2 + 1]);
                *(float2*)&outp[d * D_ + e] = o;
            }
        }
    }
    if (tid < 64) g_skp[(bh * KVCH + ch) * D_ + tid] = sk;
}

// ---------------- phase 2b: reduce chunk partials ---------------------------
__global__ __launch_bounds__(256) void reduce_kernel() {
    const int bh = blockIdx.x;
    const int tid = threadIdx.x;
    for (int idx = tid; idx < D_ * D_; idx += 256) {
        float s = 0.f;
#pragma unroll
        for (int c = 0; c < KVCH; c++) s += g_kvp[(size_t)(bh * KVCH + c) * D_ * D_ + idx];
        g_kv[(size_t)bh * D_ * D_ + idx] = s;
    }
    if (tid < 64) {
        float s = 0.f;
#pragma unroll
        for (int c = 0; c < KVCH; c++) s += g_skp[(bh * KVCH + c) * D_ + tid];
        g_sk[bh * D_ + tid] = s;
    }
}

// ---------------- phase 3: out = (q @ kv) * denom ---------------------------
__global__ __launch_bounds__(256) void out_kernel(float* __restrict__ out) {
    const int bh = blockIdx.x;
    const int lc = blockIdx.y;
    const int b = bh >> 4, h = bh & 15;

    __shared__ float qs[64][68];
    __shared__ float kvs[64][68];
    __shared__ float sks[64];
    __shared__ float den[64];

    const int tid = threadIdx.x;
    const int tx = tid & 15, ty = tid >> 4;
    const int lr = tid >> 4, lv = tid & 15;

    const __half* qb = g_qh + ((size_t)b * L_ + lc * 64) * C_ + h * D_;
#pragma unroll
    for (int i = 0; i < 4; i++) {
        const int r = lr + i * 16;
        const __half2* qp = (const __half2*)&qb[(size_t)r * C_ + lv * 4];
        float2 q0 = __half22float2(qp[0]), q1 = __half22float2(qp[1]);
        qs[r][lv * 4 + 0] = q0.x; qs[r][lv * 4 + 1] = q0.y;
        qs[r][lv * 4 + 2] = q1.x; qs[r][lv * 4 + 3] = q1.y;
        *(float4*)&kvs[r][lv * 4] = *(const float4*)&g_kv[(size_t)bh * D_ * D_ + r * D_ + lv * 4];
    }
    if (tid < 64) sks[tid] = g_sk[bh * D_ + tid];
    __syncthreads();

    if (tid < 64) {
        float s = 0.f;
#pragma unroll 16
        for (int d = 0; d < 64; d++) s += qs[tid][d] * sks[d];
        den[tid] = 1.f / (1e-6f + s);
    }
    __syncthreads();

    float acc[4][4];
#pragma unroll
    for (int i = 0; i < 4; i++)
#pragma unroll
        for (int j = 0; j < 4; j++) acc[i][j] = 0.f;

#pragma unroll 4
    for (int d = 0; d < 64; d++) {
        const float4 kv4 = *(const float4*)&kvs[d][tx * 4];
#pragma unroll
        for (int i = 0; i < 4; i++) {
            const float qv = qs[ty * 4 + i][d];
            acc[i][0] += qv * kv4.x; acc[i][1] += qv * kv4.y;
            acc[i][2] += qv * kv4.z; acc[i][3] += qv * kv4.w;
        }
    }

#pragma unroll
    for (int i = 0; i < 4; i++) {
        const int l = lc * 64 + ty * 4 + i;
        const float dn = den[ty * 4 + i];
        float4 o = make_float4(acc[i][0] * dn, acc[i][1] * dn,
                               acc[i][2] * dn, acc[i][3] * dn);
        *(float4*)&out[((size_t)b * L_ + l) * C_ + h * D_ + tx * 4] = o;
    }
}

// ---------------- launch ----------------------------------------------------
extern "C" void kernel_launch(void* const* d_in, const int* in_sizes, int n_in,
                              void* d_out, int out_size) {
    const float* query   = (const float*)d_in[0];
    const float* key     = (const float*)d_in[1];
    const float* value   = (const float*)d_in[2];
    const float* mask_q  = (const float*)d_in[3];
    const float* mask_kv = (const float*)d_in[4];
    const float* Wq = (const float*)d_in[5];
    const float* bq = (const float*)d_in[6];
    const float* Wk = (const float*)d_in[7];
    const float* bk = (const float*)d_in[8];
    const float* Wv = (const float*)d_in[9];
    const float* bv = (const float*)d_in[10];
    float* out = (float*)d_out;

    static bool attr_done = false;
    if (!attr_done) {
        cudaFuncSetAttribute(proj_all,
            cudaFuncAttributeMaxDynamicSharedMemorySize, PROJ_SMEM);
        attr_done = true;
    }

    dim3 pg(C_ / HBN_, MTOT / HBM_, 3);        // (8, 128, 3)
    dim3 cx(MTOT * C_ / 16 / 256, 3);          // (4096, 3)
    dim3 cw(C_ * C_ / 8 / 256, 3);             // (512, 3)

    cvt_x3<<<cx, 256>>>(query, key, value);
    cvt_w3<<<cw, 256>>>(Wq, Wk, Wv);

    proj_all<<<pg, 256, PROJ_SMEM>>>(bq, bk, bv, mask_q, mask_kv);

    kv_kernel<<<dim3(64, KVCH), 256>>>();
    reduce_kernel<<<64, 256>>>();
    out_kernel<<<dim3(64, 64), 256>>>(out);
}